// round 15
// baseline (speedup 1.0000x reference)
#include <cuda_runtime.h>
#include <cuda_bf16.h>
#include <cstdint>

#define NN 20000
#define EE 300000
#define HH 128
#define LL 8
#define PITCH 272
#define NSM 148

#define A_HI 0
#define A_LO 34816
#define B_HI 69632
#define G_SMEM 140288
#define W1_HI 69632
#define W2_HI 139264
#define E_RS  208896
#define E_SMEM 209408
#define N_SMEM 208896

#define BAR_PAIR(id) asm volatile("bar.sync %0, 64;" :: "r"(id) : "memory")
#define BAR_GRP(id)  asm volatile("bar.sync %0, 256;" :: "r"(id) : "memory")

// ============================ scratch globals ===============================
__device__ __align__(16) float g_x  [NN * HH];
__device__ __align__(16) float g_xs [NN * HH];
__device__ __align__(16) float g_xd [NN * HH];
__device__ __align__(16) float g_agg[NN * HH];
__device__ __align__(16) uint32_t g_ehi[(size_t)EE * 64];
__device__ __align__(16) uint32_t g_elo[(size_t)EE * 64];
__device__ int g_cursor[NN];
__device__ int g_perm[EE];
__device__ int g_rowp[EE];
__device__ int g_colp[EE];

__device__ __align__(16) __nv_bfloat16 g_wsrc[LL * 32768];
__device__ __align__(16) __nv_bfloat16 g_wdst[LL * 32768];
__device__ __align__(16) __nv_bfloat16 g_we  [LL * 32768];
__device__ __align__(16) __nv_bfloat16 g_we2 [LL * 32768];
__device__ __align__(16) __nv_bfloat16 g_wnx [LL * 32768];
__device__ __align__(16) __nv_bfloat16 g_wna [LL * 32768];
__device__ __align__(16) __nv_bfloat16 g_wn2 [LL * 32768];
__device__ __align__(16) __nv_bfloat16 g_wne2[32768];
__device__ __align__(16) __nv_bfloat16 g_wee2[32768];

// ============================ helpers =======================================
__device__ __forceinline__ uint32_t smem_u32(const void* p) {
    uint32_t a;
    asm("{ .reg .u64 t; cvta.to.shared.u64 t, %1; cvt.u32.u64 %0, t; }"
        : "=r"(a) : "l"(p));
    return a;
}
__device__ __forceinline__ void ldsm4(uint32_t addr, uint32_t r[4]) {
    asm volatile("ldmatrix.sync.aligned.m8n8.x4.shared.b16 {%0,%1,%2,%3}, [%4];"
                 : "=r"(r[0]), "=r"(r[1]), "=r"(r[2]), "=r"(r[3]) : "r"(addr));
}
__device__ __forceinline__ void mma16816(float c[4], const uint32_t a[4],
                                         const uint32_t* b) {
    asm volatile("mma.sync.aligned.m16n8k16.row.col.f32.bf16.bf16.f32 "
                 "{%0,%1,%2,%3}, {%4,%5,%6,%7}, {%8,%9}, {%0,%1,%2,%3};"
                 : "+f"(c[0]), "+f"(c[1]), "+f"(c[2]), "+f"(c[3])
                 : "r"(a[0]), "r"(a[1]), "r"(a[2]), "r"(a[3]),
                   "r"(b[0]), "r"(b[1]));
}
#define CP16(dst, src) \
    asm volatile("cp.async.cg.shared.global [%0], [%1], 16;" \
                 :: "r"(dst), "l"(src) : "memory")
#define CP_WAIT() \
    asm volatile("cp.async.commit_group;\n\tcp.async.wait_group 0;" ::: "memory")
#define REDF2(ptr, v0, v1) \
    asm volatile("red.global.add.v2.f32 [%0], {%1, %2};" \
                 :: "l"(ptr), "f"(v0), "f"(v1) : "memory")

__device__ __forceinline__ void split2(float a, float b, uint32_t& hi, uint32_t& lo) {
    asm("cvt.rn.bf16x2.f32 %0, %1, %2;" : "=r"(hi) : "f"(b), "f"(a));
    float ah = __uint_as_float(hi << 16);
    float bh = __uint_as_float(hi & 0xFFFF0000u);
    asm("cvt.rn.bf16x2.f32 %0, %1, %2;" : "=r"(lo) : "f"(b - bh), "f"(a - ah));
}

// 3-term GEMM, warp tile 32x64 (256-thread kernels); A lo at +34816
__device__ __forceinline__ void warp_gemm3(const char* sm, uint32_t b_off,
                                           int wr, int wc, int lid,
                                           float acc[2][8][4]) {
    uint32_t sb = smem_u32(sm);
    uint32_t a_base = sb + A_HI + (uint32_t)(wr * 32 + (lid & 15)) * PITCH +
                      (uint32_t)((lid >> 4) * 8) * 2;
    uint32_t b_base = sb + b_off +
        (uint32_t)(wc * 64 + ((lid >> 4) & 1) * 8 + (lid & 7)) * PITCH +
        (uint32_t)(((lid >> 3) & 1) * 8) * 2;
#pragma unroll
    for (int ks = 0; ks < 8; ks++) {
        uint32_t ko = ks * 32;
        uint32_t Ah[2][4], Al[2][4], Bh[4][4], Bl[4][4];
        ldsm4(a_base + ko, Ah[0]);
        ldsm4(a_base + 16 * PITCH + ko, Ah[1]);
        ldsm4(a_base + 34816 + ko, Al[0]);
        ldsm4(a_base + 34816 + 16 * PITCH + ko, Al[1]);
#pragma unroll
        for (int g = 0; g < 4; g++) {
            ldsm4(b_base + g * 16 * PITCH + ko, Bh[g]);
            ldsm4(b_base + 34816 + g * 16 * PITCH + ko, Bl[g]);
        }
#pragma unroll
        for (int m = 0; m < 2; m++)
#pragma unroll
            for (int g = 0; g < 4; g++)
#pragma unroll
                for (int s = 0; s < 2; s++) {
                    float* c = acc[m][g * 2 + s];
                    mma16816(c, Ah[m], &Bh[g][2 * s]);
                    mma16816(c, Al[m], &Bh[g][2 * s]);
                    mma16816(c, Ah[m], &Bl[g][2 * s]);
                }
    }
}

// 3-term GEMM, warp tile 16x64, 64-row A region at a_off (lo at +17408)
__device__ __forceinline__ void warp_gemm3_64(const char* sm, uint32_t a_off,
                                              uint32_t b_off, int wr, int wc,
                                              int lid, float acc[8][4]) {
    uint32_t sb = smem_u32(sm);
    uint32_t a_base = sb + a_off + (uint32_t)(wr * 16 + (lid & 15)) * PITCH +
                      (uint32_t)((lid >> 4) * 8) * 2;
    uint32_t b_base = sb + b_off +
        (uint32_t)(wc * 64 + ((lid >> 4) & 1) * 8 + (lid & 7)) * PITCH +
        (uint32_t)(((lid >> 3) & 1) * 8) * 2;
#pragma unroll
    for (int ks = 0; ks < 8; ks++) {
        uint32_t ko = ks * 32;
        uint32_t Ah[4], Al[4];
        ldsm4(a_base + ko, Ah);
        ldsm4(a_base + 17408 + ko, Al);
#pragma unroll
        for (int g = 0; g < 4; g++) {
            uint32_t Bh[4], Bl[4];
            ldsm4(b_base + g * 16 * PITCH + ko, Bh);
            ldsm4(b_base + 34816 + g * 16 * PITCH + ko, Bl);
#pragma unroll
            for (int s = 0; s < 2; s++) {
                float* c = acc[g * 2 + s];
                mma16816(c, Ah, &Bh[2 * s]);
                mma16816(c, Al, &Bh[2 * s]);
                mma16816(c, Ah, &Bl[2 * s]);
            }
        }
    }
}

#define ZACC(acc)                                   \
    _Pragma("unroll") for (int _m = 0; _m < 2; _m++) \
    _Pragma("unroll") for (int _n = 0; _n < 8; _n++) \
    _Pragma("unroll") for (int _q = 0; _q < 4; _q++) acc[_m][_n][_q] = 0.f;
#define ZACC1(acc)                                  \
    _Pragma("unroll") for (int _n = 0; _n < 8; _n++) \
    _Pragma("unroll") for (int _q = 0; _q < 4; _q++) acc[_n][_q] = 0.f;

template <int NT>
__device__ __forceinline__ void load_split_tile_t(const float* __restrict__ src,
                                                  int base, int maxr, char* sm) {
    for (int g = threadIdx.x; g < 2048; g += NT) {
        int r = g >> 4, c8 = (g & 15) << 3;
        int rr = min(base + r, maxr - 1);
        const float* p = src + (size_t)rr * HH + c8;
        float4 v0 = *(const float4*)p;
        float4 v1 = *(const float4*)(p + 4);
        uint32_t h0, l0, h1, l1, h2, l2, h3, l3;
        split2(v0.x, v0.y, h0, l0); split2(v0.z, v0.w, h1, l1);
        split2(v1.x, v1.y, h2, l2); split2(v1.z, v1.w, h3, l3);
        char* dst = sm + (size_t)r * PITCH + c8 * 2;
        *(uint4*)(dst + A_HI) = make_uint4(h0, h1, h2, h3);
        *(uint4*)(dst + A_LO) = make_uint4(l0, l1, l2, l3);
    }
}

// load 64-row f32 tile -> bf16 hi/lo into group buffer at ga (lo at +17408)
__device__ __forceinline__ void load_split_64(const float* __restrict__ src,
                                              int base, int maxr, char* sm,
                                              uint32_t ga, int gtid) {
    for (int g = gtid; g < 1024; g += 256) {
        int r = g >> 4, c8 = (g & 15) << 3;
        int rr = min(base + r, maxr - 1);
        const float* p = src + (size_t)rr * HH + c8;
        float4 v0 = *(const float4*)p;
        float4 v1 = *(const float4*)(p + 4);
        uint32_t h0, l0, h1, l1, h2, l2, h3, l3;
        split2(v0.x, v0.y, h0, l0); split2(v0.z, v0.w, h1, l1);
        split2(v1.x, v1.y, h2, l2); split2(v1.z, v1.w, h3, l3);
        char* dst = sm + ga + (size_t)r * PITCH + c8 * 2;
        *(uint4*)(dst) = make_uint4(h0, h1, h2, h3);
        *(uint4*)(dst + 17408) = make_uint4(l0, l1, l2, l3);
    }
}

__device__ __forceinline__ void copy_w(const __nv_bfloat16* __restrict__ w,
                                       char* sm, uint32_t off_hi) {
    const uint4* s = (const uint4*)w;
    for (int i = threadIdx.x; i < 2048; i += 256) {
        int r = i >> 4, c = i & 15;
        char* dst = sm + off_hi + (size_t)r * PITCH + c * 16;
        *(uint4*)(dst) = s[i];
        *(uint4*)(dst + 34816) = s[i + 2048];
    }
}

template <int NT>
__device__ __forceinline__ void copy_w_async(const __nv_bfloat16* __restrict__ w,
                                             uint32_t sb, uint32_t off_hi) {
    const uint4* s = (const uint4*)w;
    for (int i = threadIdx.x; i < 2048; i += NT) {
        int r = i >> 4, c = i & 15;
        uint32_t dst = sb + off_hi + (uint32_t)r * PITCH + (uint32_t)c * 16;
        CP16(dst, s + i);
        CP16(dst + 34816, s + i + 2048);
    }
}

// ============================ pack kernel ===================================
__device__ __forceinline__ void pack_store(__nv_bfloat16* b, int t, float v) {
    __nv_bfloat16 h = __float2bfloat16_rn(v);
    __nv_bfloat16 lo = __float2bfloat16_rn(v - __bfloat162float(h));
    b[t] = h;
    b[t + 16384] = lo;
}

__global__ void pack_all(const float* __restrict__ ew1, const float* __restrict__ nw1,
                         const float* __restrict__ ew2, const float* __restrict__ nw2,
                         const float* __restrict__ new2, const float* __restrict__ eew2) {
    int i = blockIdx.x * 256 + threadIdx.x;
    int m = i >> 14, t = i & 16383;
    int n = t >> 7, k = t & 127;
    const float* src;
    __nv_bfloat16* dst;
    if (m < 24) {
        int l = m / 3, j = m - l * 3;
        src = ew1 + (size_t)m * 16384;
        dst = (j == 0 ? g_wsrc : j == 1 ? g_wdst : g_we) + (size_t)l * 32768;
    } else if (m < 40) {
        int mm = m - 24, l = mm >> 1, j = mm & 1;
        src = nw1 + (size_t)mm * 16384;
        dst = (j ? g_wna : g_wnx) + (size_t)l * 32768;
    } else if (m < 48) {
        src = ew2 + (size_t)(m - 40) * 16384; dst = g_we2 + (size_t)(m - 40) * 32768;
    } else if (m < 56) {
        src = nw2 + (size_t)(m - 48) * 16384; dst = g_wn2 + (size_t)(m - 48) * 32768;
    } else if (m == 56) { src = new2; dst = g_wne2; }
    else                { src = eew2; dst = g_wee2; }
    pack_store(dst, t, src[k * HH + n]);
}

// ===================== counting sort ========================================
__global__ __launch_bounds__(1024, 1) void sort_build(const int* __restrict__ rowi) {
    extern __shared__ int sh[];
    int tid = threadIdx.x;
    for (int i = tid; i < NN; i += 1024) sh[i] = 0;
    __syncthreads();
    for (int i = tid; i < EE; i += 1024) atomicAdd(&sh[rowi[i]], 1);
    __syncthreads();
    int* sums = sh + NN;
    int base = tid * 20;
    int s = 0;
    for (int j = 0; j < 20; j++) {
        int idx = base + j;
        if (idx < NN) s += sh[idx];
    }
    sums[tid] = s;
    __syncthreads();
    for (int off = 1; off < 1024; off <<= 1) {
        int v = (tid >= off) ? sums[tid - off] : 0;
        __syncthreads();
        sums[tid] += v;
        __syncthreads();
    }
    int run = (tid == 0) ? 0 : sums[tid - 1];
    for (int j = 0; j < 20; j++) {
        int idx = base + j;
        if (idx < NN) {
            g_cursor[idx] = run;
            run += sh[idx];
        }
    }
}

__global__ void sort_permute(const int* __restrict__ rowi,
                             const int* __restrict__ coli) {
    int i = blockIdx.x * 256 + threadIdx.x;
    if (i < EE) {
        int r = rowi[i];
        int pos = atomicAdd(&g_cursor[r], 1);
        g_perm[pos] = i;
        g_rowp[pos] = r;
        g_colp[pos] = coli[i];
    }
}

// == persistent edge layer: 2 independent 256-thread groups per CTA =========
__global__ __launch_bounds__(512, 1) void edge_layer_persist(
    int l, const float* __restrict__ b1, const float* __restrict__ b2,
    int nt64, int store_e) {
    extern __shared__ __align__(16) char sm[];
    uint32_t sb = smem_u32(sm);
    int tid = threadIdx.x;
    int grp = tid >> 8, gtid = tid & 255;
    int lid = tid & 31, wid_g = gtid >> 5;
    int wr = wid_g >> 1, wc = wid_g & 1;
    int barG = 1 + grp;
    int barP = 3 + grp * 4 + wr;
    uint32_t ga = (uint32_t)grp * 34816;
    int* rs_s = (int*)(sm + E_RS) + grp * 64;

    copy_w_async<512>(g_we + (size_t)l * 32768, sb, W1_HI);
    copy_w_async<512>(g_we2 + (size_t)l * 32768, sb, W2_HI);
    CP_WAIT();
    __syncthreads();

    int lq = lid >> 2, lr = (lid & 3) * 2;
    int rA = wr * 16 + lq, rB = rA + 8;

    for (int st = blockIdx.x * 2 + grp; st < nt64; st += gridDim.x * 2) {
        int ebase = st * 64;
        BAR_GRP(barG);

        for (int g = gtid; g < 1024; g += 256) {
            int r = g >> 4, cp2 = (g & 15) << 2;
            int er = min(ebase + r, EE - 1);
            uint32_t d = sb + ga + (uint32_t)r * PITCH + (uint32_t)cp2 * 4;
            CP16(d, g_ehi + (size_t)er * 64 + cp2);
            CP16(d + 17408, g_elo + (size_t)er * 64 + cp2);
        }
        if (gtid < 64) rs_s[gtid] = g_rowp[min(ebase + gtid, EE - 1)];

        int eAg = min(ebase + rA, EE - 1), eBg = min(ebase + rB, EE - 1);
        int rowA = g_rowp[eAg], rowB = g_rowp[eBg];
        int colA = g_colp[eAg], colB = g_colp[eBg];

        float acc[8][4];
        {
            const float* xsA = g_xs + (size_t)rowA * HH;
            const float* xdA = g_xd + (size_t)colA * HH;
            const float* xsB = g_xs + (size_t)rowB * HH;
            const float* xdB = g_xd + (size_t)colB * HH;
#pragma unroll
            for (int n = 0; n < 8; n++) {
                int col = wc * 64 + n * 8 + lr;
                float2 bv = *(const float2*)(b1 + col);
                float2 sA = *(const float2*)(xsA + col);
                float2 dA = *(const float2*)(xdA + col);
                float2 sB = *(const float2*)(xsB + col);
                float2 dB = *(const float2*)(xdB + col);
                acc[n][0] = bv.x + sA.x + dA.x;
                acc[n][1] = bv.y + sA.y + dA.y;
                acc[n][2] = bv.x + sB.x + dB.x;
                acc[n][3] = bv.y + sB.y + dB.y;
            }
        }
        CP_WAIT();
        BAR_GRP(barG);

        warp_gemm3_64(sm, ga, W1_HI, wr, wc, lid, acc);
        BAR_PAIR(barP);

#pragma unroll
        for (int n = 0; n < 8; n++) {
            int col = wc * 64 + n * 8 + lr;
            float* c = acc[n];
            uint32_t hi, lo;
            split2(fmaxf(c[0], 0.f), fmaxf(c[1], 0.f), hi, lo);
            *(uint32_t*)(sm + ga + (size_t)rA * PITCH + col * 2) = hi;
            *(uint32_t*)(sm + ga + 17408 + (size_t)rA * PITCH + col * 2) = lo;
            split2(fmaxf(c[2], 0.f), fmaxf(c[3], 0.f), hi, lo);
            *(uint32_t*)(sm + ga + (size_t)rB * PITCH + col * 2) = hi;
            *(uint32_t*)(sm + ga + 17408 + (size_t)rB * PITCH + col * 2) = lo;
        }
        BAR_PAIR(barP);

        ZACC1(acc);
        warp_gemm3_64(sm, ga, W2_HI, wr, wc, lid, acc);
        BAR_GRP(barG);

        {
            int eA = ebase + rA, eB = ebase + rB;
#pragma unroll
            for (int n = 0; n < 8; n++) {
                int col = wc * 64 + n * 8 + lr;
                float2 bv = *(const float2*)(b2 + col);
                float* c = acc[n];
                float vx0 = 0.f, vy0 = 0.f, vx1 = 0.f, vy1 = 0.f;
                if (eA < EE) {
                    vx0 = c[0] + bv.x; vy0 = c[1] + bv.y;
                    if (store_e) {
                        uint32_t hi, lo;
                        split2(vx0, vy0, hi, lo);
                        g_ehi[(size_t)eA * 64 + (col >> 1)] = hi;
                        g_elo[(size_t)eA * 64 + (col >> 1)] = lo;
                    }
                }
                if (eB < EE) {
                    vx1 = c[2] + bv.x; vy1 = c[3] + bv.y;
                    if (store_e) {
                        uint32_t hi, lo;
                        split2(vx1, vy1, hi, lo);
                        g_ehi[(size_t)eB * 64 + (col >> 1)] = hi;
                        g_elo[(size_t)eB * 64 + (col >> 1)] = lo;
                    }
                }
                *(float2*)(sm + ga + (size_t)rA * 544 + col * 4) =
                    make_float2(vx0, vy0);
                *(float2*)(sm + ga + (size_t)rB * 544 + col * 4) =
                    make_float2(vx1, vy1);
            }
        }
        BAR_GRP(barG);

        {
            int cp = (gtid & 63) * 2, q = gtid >> 6;
            int r0 = q * 16, r1 = r0 + 16;
            float s0 = 0.f, s1 = 0.f;
            int prev = rs_s[r0];
            for (int r = r0; r < r1; r++) {
                float2 v = *(const float2*)(sm + ga + (size_t)r * 544 + cp * 4);
                s0 += v.x; s1 += v.y;
                int nxt = (r + 1 < r1) ? rs_s[r + 1] : -2;
                if (nxt != prev) {
                    REDF2(g_agg + (size_t)prev * HH + cp, s0, s1);
                    s0 = 0.f; s1 = 0.f;
                    prev = nxt;
                }
            }
        }
    }
}

// == node layer + next xs/xd: 148 persistent CTAs, 2 lock-step groups =======
__global__ __launch_bounds__(512, 1) void node_xsxd(
    int l, const float* __restrict__ b1, const float* __restrict__ b2,
    int do_next, int nt64) {
    extern __shared__ __align__(16) char sm[];
    uint32_t sb = smem_u32(sm);
    int tid = threadIdx.x;
    int grp = tid >> 8, gtid = tid & 255;
    int lid = tid & 31, wid_g = gtid >> 5;
    int wr = wid_g >> 1, wc = wid_g & 1;
    int barP = 3 + grp * 4 + wr;
    uint32_t ga = (uint32_t)grp * 34816;
    int lq = lid >> 2, lr = (lid & 3) * 2;
    int rA = wr * 16 + lq, rB = rA + 8;

    int nit = (nt64 - 2 * (int)blockIdx.x + 295) / 296;  // group0 bound (max)

    for (int it = 0; it < nit; it++) {
        int st = it * 296 + blockIdx.x * 2 + grp;
        int base = st * 64;   // base >= NN iff st >= nt64 -> store guards mask

        __syncthreads();   // prior iter done with W regions + ga
        copy_w_async<512>(g_wnx + (size_t)l * 32768, sb, W1_HI);
        copy_w_async<512>(g_wna + (size_t)l * 32768, sb, W2_HI);
        load_split_64(g_x, base, NN, sm, ga, gtid);
        CP_WAIT();
        __syncthreads();   // S1: x tile + wnx/wna ready

        float acc[8][4];
        ZACC1(acc);
        warp_gemm3_64(sm, ga, W1_HI, wr, wc, lid, acc);      // x @ wnx
        __syncthreads();   // S2: W1 + ga free

        copy_w_async<512>(g_wn2 + (size_t)l * 32768, sb, W1_HI);
        load_split_64(g_agg, base, NN, sm, ga, gtid);
        CP_WAIT();
        __syncthreads();   // S3: agg + wn2 ready
        warp_gemm3_64(sm, ga, W2_HI, wr, wc, lid, acc);      // += agg @ wna
        __syncthreads();   // S4: W2 + ga free

        if (do_next)
            copy_w_async<512>(g_wsrc + (size_t)(l + 1) * 32768, sb, W2_HI);
#pragma unroll
        for (int n = 0; n < 8; n++) {
            int col = wc * 64 + n * 8 + lr;
            float2 bv = *(const float2*)(b1 + col);
            float* c = acc[n];
            uint32_t hi, lo;
            split2(fmaxf(c[0] + bv.x, 0.f), fmaxf(c[1] + bv.y, 0.f), hi, lo);
            *(uint32_t*)(sm + ga + (size_t)rA * PITCH + col * 2) = hi;
            *(uint32_t*)(sm + ga + 17408 + (size_t)rA * PITCH + col * 2) = lo;
            split2(fmaxf(c[2] + bv.x, 0.f), fmaxf(c[3] + bv.y, 0.f), hi, lo);
            *(uint32_t*)(sm + ga + (size_t)rB * PITCH + col * 2) = hi;
            *(uint32_t*)(sm + ga + 17408 + (size_t)rB * PITCH + col * 2) = lo;
        }
        CP_WAIT();
        BAR_PAIR(barP);    // both column halves of h written

        ZACC1(acc);
        warp_gemm3_64(sm, ga, W1_HI, wr, wc, lid, acc);      // h @ wn2
        __syncthreads();   // S5: W1 + ga(h) free

        if (do_next)
            copy_w_async<512>(g_wdst + (size_t)(l + 1) * 32768, sb, W1_HI);
#pragma unroll
        for (int n = 0; n < 8; n++) {
            int col = wc * 64 + n * 8 + lr;
            float2 bv = *(const float2*)(b2 + col);
            float* c = acc[n];
            uint32_t hi, lo;
            if (base + rA < NN) {
                float* xp = g_x + (size_t)(base + rA) * HH + col;
                float2 xv = *(float2*)xp;
                float vx = c[0] + bv.x + xv.x, vy = c[1] + bv.y + xv.y;
                *(float2*)xp = make_float2(vx, vy);
                split2(vx, vy, hi, lo);
            } else split2(0.f, 0.f, hi, lo);
            *(uint32_t*)(sm + ga + (size_t)rA * PITCH + col * 2) = hi;
            *(uint32_t*)(sm + ga + 17408 + (size_t)rA * PITCH + col * 2) = lo;
            if (base + rB < NN) {
                float* xp = g_x + (size_t)(base + rB) * HH + col;
                float2 xv = *(float2*)xp;
                float vx = c[2] + bv.x + xv.x, vy = c[3] + bv.y + xv.y;
                *(float2*)xp = make_float2(vx, vy);
                split2(vx, vy, hi, lo);
            } else split2(0.f, 0.f, hi, lo);
            *(uint32_t*)(sm + ga + (size_t)rB * PITCH + col * 2) = hi;
            *(uint32_t*)(sm + ga + 17408 + (size_t)rB * PITCH + col * 2) = lo;
        }
        for (int i = gtid; i < 2048; i += 256) {
            int r = i >> 5, c4 = i & 31;
            if (base + r < NN)
                ((float4*)g_agg)[(size_t)(base + r) * 32 + c4] =
                    make_float4(0.f, 0.f, 0.f, 0.f);
        }
        if (!do_next) continue;
        CP_WAIT();
        __syncthreads();   // S6: ga(x_new) complete; wsrc/wdst landed

        ZACC1(acc);
        warp_gemm3_64(sm, ga, W2_HI, wr, wc, lid, acc);      // x_new @ wsrc
#pragma unroll
        for (int n = 0; n < 8; n++) {
            int col = wc * 64 + n * 8 + lr;
            float* c = acc[n];
            if (base + rA < NN)
                *(float2*)(g_xs + (size_t)(base + rA) * HH + col) =
                    make_float2(c[0], c[1]);
            if (base + rB < NN)
                *(float2*)(g_xs + (size_t)(base + rB) * HH + col) =
                    make_float2(c[2], c[3]);
        }

        ZACC1(acc);
        warp_gemm3_64(sm, ga, W1_HI, wr, wc, lid, acc);      // x_new @ wdst
#pragma unroll
        for (int n = 0; n < 8; n++) {
            int col = wc * 64 + n * 8 + lr;
            float* c = acc[n];
            if (base + rA < NN)
                *(float2*)(g_xd + (size_t)(base + rA) * HH + col) =
                    make_float2(c[0], c[1]);
            if (base + rB < NN)
                *(float2*)(g_xd + (size_t)(base + rB) * HH + col) =
                    make_float2(c[2], c[3]);
        }
    }
}

// ====== node encoder fused with xs/xd projection of layer 0 + agg zero =====
__global__ __launch_bounds__(256, 1) void encoder_node_fused(
    const float* __restrict__ in, const float* __restrict__ w1,
    const float* __restrict__ b1, const float* __restrict__ b2) {
    extern __shared__ __align__(16) char sm[];
    int tid = threadIdx.x, lid = tid & 31, wid = tid >> 5;
    int wr = wid >> 1, wc = wid & 1;
    int base = blockIdx.x * 128;
    int lq = lid >> 2, lr = (lid & 3) * 2;

    for (int g = tid; g < 2048; g += 256) {
        int r = g >> 4, c8 = (g & 15) << 3;
        int rr = min(base + r, NN - 1);
        float vin[6];
#pragma unroll
        for (int k = 0; k < 6; k++) vin[k] = in[(size_t)rr * 6 + k];
        float h[8];
#pragma unroll
        for (int c = 0; c < 8; c++) {
            int cc = c8 + c;
            float s = b1[cc];
#pragma unroll
            for (int k = 0; k < 6; k++) s += vin[k] * w1[k * HH + cc];
            h[c] = fmaxf(s, 0.f);
        }
        uint32_t hv[4], lv[4];
        split2(h[0], h[1], hv[0], lv[0]);
        split2(h[2], h[3], hv[1], lv[1]);
        split2(h[4], h[5], hv[2], lv[2]);
        split2(h[6], h[7], hv[3], lv[3]);
        char* dst = sm + (size_t)r * PITCH + c8 * 2;
        *(uint4*)(dst + A_HI) = make_uint4(hv[0], hv[1], hv[2], hv[3]);
        *(uint4*)(dst + A_LO) = make_uint4(lv[0], lv[1], lv[2], lv[3]);
    }
    copy_w(g_wne2, sm, B_HI);
    __syncthreads();

    float acc[2][8][4];
    ZACC(acc);
    warp_gemm3(sm, B_HI, wr, wc, lid, acc);
    __syncthreads();

#pragma unroll
    for (int m = 0; m < 2; m++) {
        int rA = wr * 32 + m * 16 + lq, rB = rA + 8;
#pragma unroll
        for (int n = 0; n < 8; n++) {
            int col = wc * 64 + n * 8 + lr;
            float2 bv = *(const float2*)(b2 + col);
            float* c = acc[m][n];
            float vx0 = c[0] + bv.x, vy0 = c[1] + bv.y;
            float vx1 = c[2] + bv.x, vy1 = c[3] + bv.y;
            uint32_t hi, lo;
            if (base + rA < NN)
                *(float2*)(g_x + (size_t)(base + rA) * HH + col) =
                    make_float2(vx0, vy0);
            split2(vx0, vy0, hi, lo);
            *(uint32_t*)(sm + A_HI + (size_t)rA * PITCH + col * 2) = hi;
            *(uint32_t*)(sm + A_LO + (size_t)rA * PITCH + col * 2) = lo;
            if (base + rB < NN)
                *(float2*)(g_x + (size_t)(base + rB) * HH + col) =
                    make_float2(vx1, vy1);
            split2(vx1, vy1, hi, lo);
            *(uint32_t*)(sm + A_HI + (size_t)rB * PITCH + col * 2) = hi;
            *(uint32_t*)(sm + A_LO + (size_t)rB * PITCH + col * 2) = lo;
        }
    }
    for (int i = tid; i < 4096; i += 256) {
        int r = i >> 5, c4 = i & 31;
        if (base + r < NN)
            ((float4*)g_agg)[(size_t)(base + r) * 32 + c4] =
                make_float4(0.f, 0.f, 0.f, 0.f);
    }
    copy_w(g_wsrc, sm, B_HI);
    __syncthreads();
    ZACC(acc);
    warp_gemm3(sm, B_HI, wr, wc, lid, acc);
#pragma unroll
    for (int m = 0; m < 2; m++) {
        int rA = wr * 32 + m * 16 + lq, rB = rA + 8;
#pragma unroll
        for (int n = 0; n < 8; n++) {
            int col = wc * 64 + n * 8 + lr;
            float* c = acc[m][n];
            if (base + rA < NN)
                *(float2*)(g_xs + (size_t)(base + rA) * HH + col) =
                    make_float2(c[0], c[1]);
            if (base + rB < NN)
                *(float2*)(g_xs + (size_t)(base + rB) * HH + col) =
                    make_float2(c[2], c[3]);
        }
    }
    __syncthreads();
    copy_w(g_wdst, sm, B_HI);
    __syncthreads();
    ZACC(acc);
    warp_gemm3(sm, B_HI, wr, wc, lid, acc);
#pragma unroll
    for (int m = 0; m < 2; m++) {
        int rA = wr * 32 + m * 16 + lq, rB = rA + 8;
#pragma unroll
        for (int n = 0; n < 8; n++) {
            int col = wc * 64 + n * 8 + lr;
            float* c = acc[m][n];
            if (base + rA < NN)
                *(float2*)(g_xd + (size_t)(base + rA) * HH + col) =
                    make_float2(c[0], c[1]);
            if (base + rB < NN)
                *(float2*)(g_xd + (size_t)(base + rB) * HH + col) =
                    make_float2(c[2], c[3]);
        }
    }
}

// ==== edge encoder: 2 independent 256-thread groups, W shared, PERMUTED ====
__global__ __launch_bounds__(512, 1) void encoder_edge(
    const float* __restrict__ in, const float* __restrict__ w1,
    const float* __restrict__ b1, const float* __restrict__ b2, int nt64) {
    extern __shared__ __align__(16) char sm[];
    uint32_t sb = smem_u32(sm);
    int tid = threadIdx.x;
    int grp = tid >> 8, gtid = tid & 255;
    int lid = tid & 31, wid_g = gtid >> 5;
    int wr = wid_g >> 1, wc = wid_g & 1;
    int barG = 1 + grp;
    uint32_t ga = (uint32_t)grp * 34816;

    copy_w_async<512>(g_wee2, sb, B_HI);
    CP_WAIT();
    __syncthreads();
    int lq = lid >> 2, lr = (lid & 3) * 2;
    int rA = wr * 16 + lq, rB = rA + 8;

    for (int st = blockIdx.x * 2 + grp; st < nt64; st += gridDim.x * 2) {
        int base = st * 64;
        BAR_GRP(barG);
        for (int g = gtid; g < 1024; g += 256) {
            int r = g >> 4, c8 = (g & 15) << 3;
            int rr = min(base + r, EE - 1);
            int src = g_perm[rr];
            float vin[3];
#pragma unroll
            for (int k = 0; k < 3; k++) vin[k] = in[(size_t)src * 3 + k];
            float h[8];
#pragma unroll
            for (int c = 0; c < 8; c++) {
                int cc = c8 + c;
                float s = b1[cc];
#pragma unroll
                for (int k = 0; k < 3; k++) s += vin[k] * w1[k * HH + cc];
                h[c] = fmaxf(s, 0.f);
            }
            uint32_t hv[4], lv[4];
            split2(h[0], h[1], hv[0], lv[0]);
            split2(h[2], h[3], hv[1], lv[1]);
            split2(h[4], h[5], hv[2], lv[2]);
            split2(h[6], h[7], hv[3], lv[3]);
            char* dst = sm + ga + (size_t)r * PITCH + c8 * 2;
            *(uint4*)(dst) = make_uint4(hv[0], hv[1], hv[2], hv[3]);
            *(uint4*)(dst + 17408) = make_uint4(lv[0], lv[1], lv[2], lv[3]);
        }
        BAR_GRP(barG);

        float acc[8][4];
        ZACC1(acc);
        warp_gemm3_64(sm, ga, B_HI, wr, wc, lid, acc);

#pragma unroll
        for (int n = 0; n < 8; n++) {
            int col = wc * 64 + n * 8 + lr;
            float2 bv = *(const float2*)(b2 + col);
            float* c = acc[n];
            uint32_t hi, lo;
            if (base + rA < EE) {
                split2(c[0] + bv.x, c[1] + bv.y, hi, lo);
                g_ehi[(size_t)(base + rA) * 64 + (col >> 1)] = hi;
                g_elo[(size_t)(base + rA) * 64 + (col >> 1)] = lo;
            }
            if (base + rB < EE) {
                split2(c[2] + bv.x, c[3] + bv.y, hi, lo);
                g_ehi[(size_t)(base + rB) * 64 + (col >> 1)] = hi;
                g_elo[(size_t)(base + rB) * 64 + (col >> 1)] = lo;
            }
        }
    }
}

// ============================ decoder (scalar) ==============================
__global__ __launch_bounds__(256) void decoder_kernel(
    const float* __restrict__ w1, const float* __restrict__ b1,
    const float* __restrict__ w2, const float* __restrict__ b2,
    float* __restrict__ out) {
    __shared__ __align__(16) float As[64 * HH];
    int tid = threadIdx.x;
    int base = blockIdx.x * 64;
    int lane = tid & 31, wrow = tid >> 5;
    int j0 = lane * 4, r0 = wrow * 8;

    for (int i = tid; i < 64 * 32; i += 256) {
        int r = i >> 5, c4 = i & 31;
        int nr = min(base + r, NN - 1);
        ((float4*)As)[r * 32 + c4] = ((const float4*)g_x)[(size_t)nr * 32 + c4];
    }
    __syncthreads();

    float acc[8][4];
    float4 bb = *(const float4*)(b1 + j0);
#pragma unroll
    for (int r = 0; r < 8; r++) {
        acc[r][0] = bb.x; acc[r][1] = bb.y; acc[r][2] = bb.z; acc[r][3] = bb.w;
    }
#pragma unroll 2
    for (int k4 = 0; k4 < 32; k4++) {
        const float* wr = w1 + (k4 * 4) * HH + j0;
        float4 w0 = *(const float4*)(wr);
        float4 w1v = *(const float4*)(wr + HH);
        float4 w2v = *(const float4*)(wr + 2 * HH);
        float4 w3v = *(const float4*)(wr + 3 * HH);
#pragma unroll
        for (int r = 0; r < 8; r++) {
            float4 a = *(const float4*)(As + (r0 + r) * HH + k4 * 4);
            acc[r][0] += a.x * w0.x + a.y * w1v.x + a.z * w2v.x + a.w * w3v.x;
            acc[r][1] += a.x * w0.y + a.y * w1v.y + a.z * w2v.y + a.w * w3v.y;
            acc[r][2] += a.x * w0.z + a.y * w1v.z + a.z * w2v.z + a.w * w3v.z;
            acc[r][3] += a.x * w0.w + a.y * w1v.w + a.z * w2v.w + a.w * w3v.w;
        }
    }
    __syncthreads();
#pragma unroll
    for (int r = 0; r < 8; r++) {
        float4 h = make_float4(fmaxf(acc[r][0], 0.f), fmaxf(acc[r][1], 0.f),
                               fmaxf(acc[r][2], 0.f), fmaxf(acc[r][3], 0.f));
        *(float4*)(As + (r0 + r) * HH + j0) = h;
    }
    __syncthreads();

    if (tid < 192) {
        int r = tid / 3, c = tid - r * 3;
        float s = b2[c];
#pragma unroll 4
        for (int k = 0; k < HH; k++) s += As[r * HH + k] * w2[k * 3 + c];
        int nr = base + r;
        if (nr < NN) out[nr * 3 + c] = s;
    }
}

// ============================================================================
extern "C" void kernel_launch(void* const* d_in, const int* in_sizes, int n_in,
                              void* d_out, int out_size) {
    const float* x_in    = (const float*)d_in[0];
    const float* eattr   = (const float*)d_in[1];
    const float* ne_w1   = (const float*)d_in[2];
    const float* ne_b1   = (const float*)d_in[3];
    const float* ne_w2   = (const float*)d_in[4];
    const float* ne_b2   = (const float*)d_in[5];
    const float* ee_w1   = (const float*)d_in[6];
    const float* ee_b1   = (const float*)d_in[7];
    const float* ee_w2   = (const float*)d_in[8];
    const float* ee_b2   = (const float*)d_in[9];
    const float* edge_w1 = (const float*)d_in[10];
    const float* edge_b1 = (const float*)d_in[11];
    const float* edge_w2 = (const float*)d_in[12];
    const float* edge_b2 = (const float*)d_in[13];
    const float* node_w1 = (const float*)d_in[14];
    const float* node_b1 = (const float*)d_in[15];
    const float* node_w2 = (const float*)d_in[16];
    const float* node_b2 = (const float*)d_in[17];
    const float* nd_w1   = (const float*)d_in[18];
    const float* nd_b1   = (const float*)d_in[19];
    const float* nd_w2   = (const float*)d_in[20];
    const float* nd_b2   = (const float*)d_in[21];
    const int*   eidx    = (const int*)d_in[22];
    const int*   rowi    = eidx;
    const int*   coli    = eidx + EE;

    cudaFuncSetAttribute(edge_layer_persist,
                         cudaFuncAttributeMaxDynamicSharedMemorySize, E_SMEM);
    cudaFuncSetAttribute(node_xsxd,
                         cudaFuncAttributeMaxDynamicSharedMemorySize, N_SMEM);
    cudaFuncSetAttribute(encoder_node_fused,
                         cudaFuncAttributeMaxDynamicSharedMemorySize, G_SMEM);
    cudaFuncSetAttribute(encoder_edge,
                         cudaFuncAttributeMaxDynamicSharedMemorySize, G_SMEM);
    cudaFuncSetAttribute(sort_build,
                         cudaFuncAttributeMaxDynamicSharedMemorySize,
                         (NN + 1024) * 4);

    const int TB_N = (NN + 127) / 128;   // 157
    const int NT64E = (EE + 63) / 64;    // 4688
    const int NT64N = (NN + 63) / 64;    // 313

    pack_all<<<58 * 64, 256>>>(edge_w1, node_w1, edge_w2, node_w2, ne_w2, ee_w2);
    sort_build<<<1, 1024, (NN + 1024) * 4>>>(rowi);
    sort_permute<<<(EE + 255) / 256, 256>>>(rowi, coli);

    encoder_edge<<<NSM, 512, G_SMEM>>>(eattr, ee_w1, ee_b1, ee_b2, NT64E);
    encoder_node_fused<<<TB_N, 256, G_SMEM>>>(x_in, ne_w1, ne_b1, ne_b2);

    for (int l = 0; l < LL; l++) {
        edge_layer_persist<<<NSM, 512, E_SMEM>>>(l, edge_b1 + l * HH,
                                                 edge_b2 + l * HH,
                                                 NT64E, l < LL - 1 ? 1 : 0);
        node_xsxd<<<NSM, 512, N_SMEM>>>(l, node_b1 + l * HH,
                                        node_b2 + l * HH,
                                        l < LL - 1 ? 1 : 0, NT64N);
    }

    decoder_kernel<<<(NN + 63) / 64, 256>>>(nd_w1, nd_b1, nd_w2, nd_b2,
                                            (float*)d_out);
}

// round 16
// speedup vs baseline: 1.0111x; 1.0111x over previous
#include <cuda_runtime.h>
#include <cuda_bf16.h>
#include <cstdint>

#define NN 20000
#define EE 300000
#define HH 128
#define LL 8
#define PITCH 272
#define NSM 148

#define A_HI 0
#define A_LO 34816
#define B_HI 69632
#define G_SMEM 140288
#define W1_HI 69632
#define W2_HI 139264
#define E_RS  208896
#define E_SMEM 209408
#define N_SMEM 208896

#define BAR_PAIR(id) asm volatile("bar.sync %0, 64;" :: "r"(id) : "memory")
#define BAR_GRP(id)  asm volatile("bar.sync %0, 256;" :: "r"(id) : "memory")

// ============================ scratch globals ===============================
__device__ __align__(16) float g_x  [NN * HH];
__device__ __align__(16) float g_xs [NN * HH];
__device__ __align__(16) float g_xd [NN * HH];
__device__ __align__(16) float g_agg[NN * HH];
__device__ __align__(16) uint32_t g_ehi[(size_t)EE * 64];
__device__ __align__(16) uint32_t g_elo[(size_t)EE * 64];
__device__ int g_cursor[NN];
__device__ int g_perm[EE];
__device__ int g_rowp[EE];
__device__ int g_colp[EE];

__device__ __align__(16) __nv_bfloat16 g_wsrc[LL * 32768];
__device__ __align__(16) __nv_bfloat16 g_wdst[LL * 32768];
__device__ __align__(16) __nv_bfloat16 g_we  [LL * 32768];
__device__ __align__(16) __nv_bfloat16 g_we2 [LL * 32768];
__device__ __align__(16) __nv_bfloat16 g_wnx [LL * 32768];
__device__ __align__(16) __nv_bfloat16 g_wna [LL * 32768];
__device__ __align__(16) __nv_bfloat16 g_wn2 [LL * 32768];
__device__ __align__(16) __nv_bfloat16 g_wne2[32768];
__device__ __align__(16) __nv_bfloat16 g_wee2[32768];
__device__ __align__(16) __nv_bfloat16 g_wnd1[32768];

// ============================ helpers =======================================
__device__ __forceinline__ uint32_t smem_u32(const void* p) {
    uint32_t a;
    asm("{ .reg .u64 t; cvta.to.shared.u64 t, %1; cvt.u32.u64 %0, t; }"
        : "=r"(a) : "l"(p));
    return a;
}
__device__ __forceinline__ void ldsm4(uint32_t addr, uint32_t r[4]) {
    asm volatile("ldmatrix.sync.aligned.m8n8.x4.shared.b16 {%0,%1,%2,%3}, [%4];"
                 : "=r"(r[0]), "=r"(r[1]), "=r"(r[2]), "=r"(r[3]) : "r"(addr));
}
__device__ __forceinline__ void mma16816(float c[4], const uint32_t a[4],
                                         const uint32_t* b) {
    asm volatile("mma.sync.aligned.m16n8k16.row.col.f32.bf16.bf16.f32 "
                 "{%0,%1,%2,%3}, {%4,%5,%6,%7}, {%8,%9}, {%0,%1,%2,%3};"
                 : "+f"(c[0]), "+f"(c[1]), "+f"(c[2]), "+f"(c[3])
                 : "r"(a[0]), "r"(a[1]), "r"(a[2]), "r"(a[3]),
                   "r"(b[0]), "r"(b[1]));
}
#define CP16(dst, src) \
    asm volatile("cp.async.cg.shared.global [%0], [%1], 16;" \
                 :: "r"(dst), "l"(src) : "memory")
#define CP_WAIT() \
    asm volatile("cp.async.commit_group;\n\tcp.async.wait_group 0;" ::: "memory")
#define REDF2(ptr, v0, v1) \
    asm volatile("red.global.add.v2.f32 [%0], {%1, %2};" \
                 :: "l"(ptr), "f"(v0), "f"(v1) : "memory")

__device__ __forceinline__ void split2(float a, float b, uint32_t& hi, uint32_t& lo) {
    asm("cvt.rn.bf16x2.f32 %0, %1, %2;" : "=r"(hi) : "f"(b), "f"(a));
    float ah = __uint_as_float(hi << 16);
    float bh = __uint_as_float(hi & 0xFFFF0000u);
    asm("cvt.rn.bf16x2.f32 %0, %1, %2;" : "=r"(lo) : "f"(b - bh), "f"(a - ah));
}

// 3-term GEMM, warp tile 32x64 (256-thread kernels); A lo at +34816
__device__ __forceinline__ void warp_gemm3(const char* sm, uint32_t b_off,
                                           int wr, int wc, int lid,
                                           float acc[2][8][4]) {
    uint32_t sb = smem_u32(sm);
    uint32_t a_base = sb + A_HI + (uint32_t)(wr * 32 + (lid & 15)) * PITCH +
                      (uint32_t)((lid >> 4) * 8) * 2;
    uint32_t b_base = sb + b_off +
        (uint32_t)(wc * 64 + ((lid >> 4) & 1) * 8 + (lid & 7)) * PITCH +
        (uint32_t)(((lid >> 3) & 1) * 8) * 2;
#pragma unroll
    for (int ks = 0; ks < 8; ks++) {
        uint32_t ko = ks * 32;
        uint32_t Ah[2][4], Al[2][4], Bh[4][4], Bl[4][4];
        ldsm4(a_base + ko, Ah[0]);
        ldsm4(a_base + 16 * PITCH + ko, Ah[1]);
        ldsm4(a_base + 34816 + ko, Al[0]);
        ldsm4(a_base + 34816 + 16 * PITCH + ko, Al[1]);
#pragma unroll
        for (int g = 0; g < 4; g++) {
            ldsm4(b_base + g * 16 * PITCH + ko, Bh[g]);
            ldsm4(b_base + 34816 + g * 16 * PITCH + ko, Bl[g]);
        }
#pragma unroll
        for (int m = 0; m < 2; m++)
#pragma unroll
            for (int g = 0; g < 4; g++)
#pragma unroll
                for (int s = 0; s < 2; s++) {
                    float* c = acc[m][g * 2 + s];
                    mma16816(c, Ah[m], &Bh[g][2 * s]);
                    mma16816(c, Al[m], &Bh[g][2 * s]);
                    mma16816(c, Ah[m], &Bl[g][2 * s]);
                }
    }
}

// 3-term GEMM, warp tile 16x64, A region 128 rows (512-thread kernels)
__device__ __forceinline__ void warp_gemm3_16(const char* sm, uint32_t b_off,
                                              int wr, int wc, int lid,
                                              float acc[8][4]) {
    uint32_t sb = smem_u32(sm);
    uint32_t a_base = sb + A_HI + (uint32_t)(wr * 16 + (lid & 15)) * PITCH +
                      (uint32_t)((lid >> 4) * 8) * 2;
    uint32_t b_base = sb + b_off +
        (uint32_t)(wc * 64 + ((lid >> 4) & 1) * 8 + (lid & 7)) * PITCH +
        (uint32_t)(((lid >> 3) & 1) * 8) * 2;
#pragma unroll
    for (int ks = 0; ks < 8; ks++) {
        uint32_t ko = ks * 32;
        uint32_t Ah[4], Al[4];
        ldsm4(a_base + ko, Ah);
        ldsm4(a_base + 34816 + ko, Al);
#pragma unroll
        for (int g = 0; g < 4; g++) {
            uint32_t Bh[4], Bl[4];
            ldsm4(b_base + g * 16 * PITCH + ko, Bh);
            ldsm4(b_base + 34816 + g * 16 * PITCH + ko, Bl);
#pragma unroll
            for (int s = 0; s < 2; s++) {
                float* c = acc[g * 2 + s];
                mma16816(c, Ah, &Bh[2 * s]);
                mma16816(c, Al, &Bh[2 * s]);
                mma16816(c, Ah, &Bl[2 * s]);
            }
        }
    }
}

// 3-term GEMM, warp tile 16x64, 64-row A region at a_off (lo at +17408)
__device__ __forceinline__ void warp_gemm3_64(const char* sm, uint32_t a_off,
                                              uint32_t b_off, int wr, int wc,
                                              int lid, float acc[8][4]) {
    uint32_t sb = smem_u32(sm);
    uint32_t a_base = sb + a_off + (uint32_t)(wr * 16 + (lid & 15)) * PITCH +
                      (uint32_t)((lid >> 4) * 8) * 2;
    uint32_t b_base = sb + b_off +
        (uint32_t)(wc * 64 + ((lid >> 4) & 1) * 8 + (lid & 7)) * PITCH +
        (uint32_t)(((lid >> 3) & 1) * 8) * 2;
#pragma unroll
    for (int ks = 0; ks < 8; ks++) {
        uint32_t ko = ks * 32;
        uint32_t Ah[4], Al[4];
        ldsm4(a_base + ko, Ah);
        ldsm4(a_base + 17408 + ko, Al);
#pragma unroll
        for (int g = 0; g < 4; g++) {
            uint32_t Bh[4], Bl[4];
            ldsm4(b_base + g * 16 * PITCH + ko, Bh);
            ldsm4(b_base + 34816 + g * 16 * PITCH + ko, Bl);
#pragma unroll
            for (int s = 0; s < 2; s++) {
                float* c = acc[g * 2 + s];
                mma16816(c, Ah, &Bh[2 * s]);
                mma16816(c, Al, &Bh[2 * s]);
                mma16816(c, Ah, &Bl[2 * s]);
            }
        }
    }
}

#define ZACC(acc)                                   \
    _Pragma("unroll") for (int _m = 0; _m < 2; _m++) \
    _Pragma("unroll") for (int _n = 0; _n < 8; _n++) \
    _Pragma("unroll") for (int _q = 0; _q < 4; _q++) acc[_m][_n][_q] = 0.f;
#define ZACC1(acc)                                  \
    _Pragma("unroll") for (int _n = 0; _n < 8; _n++) \
    _Pragma("unroll") for (int _q = 0; _q < 4; _q++) acc[_n][_q] = 0.f;

template <int NT>
__device__ __forceinline__ void load_split_tile_t(const float* __restrict__ src,
                                                  int base, int maxr, char* sm) {
    for (int g = threadIdx.x; g < 2048; g += NT) {
        int r = g >> 4, c8 = (g & 15) << 3;
        int rr = min(base + r, maxr - 1);
        const float* p = src + (size_t)rr * HH + c8;
        float4 v0 = *(const float4*)p;
        float4 v1 = *(const float4*)(p + 4);
        uint32_t h0, l0, h1, l1, h2, l2, h3, l3;
        split2(v0.x, v0.y, h0, l0); split2(v0.z, v0.w, h1, l1);
        split2(v1.x, v1.y, h2, l2); split2(v1.z, v1.w, h3, l3);
        char* dst = sm + (size_t)r * PITCH + c8 * 2;
        *(uint4*)(dst + A_HI) = make_uint4(h0, h1, h2, h3);
        *(uint4*)(dst + A_LO) = make_uint4(l0, l1, l2, l3);
    }
}

__device__ __forceinline__ void copy_w(const __nv_bfloat16* __restrict__ w,
                                       char* sm, uint32_t off_hi) {
    const uint4* s = (const uint4*)w;
    for (int i = threadIdx.x; i < 2048; i += 256) {
        int r = i >> 4, c = i & 15;
        char* dst = sm + off_hi + (size_t)r * PITCH + c * 16;
        *(uint4*)(dst) = s[i];
        *(uint4*)(dst + 34816) = s[i + 2048];
    }
}

template <int NT>
__device__ __forceinline__ void copy_w_async(const __nv_bfloat16* __restrict__ w,
                                             uint32_t sb, uint32_t off_hi) {
    const uint4* s = (const uint4*)w;
    for (int i = threadIdx.x; i < 2048; i += NT) {
        int r = i >> 4, c = i & 15;
        uint32_t dst = sb + off_hi + (uint32_t)r * PITCH + (uint32_t)c * 16;
        CP16(dst, s + i);
        CP16(dst + 34816, s + i + 2048);
    }
}

// ============================ pack kernel ===================================
__device__ __forceinline__ void pack_store(__nv_bfloat16* b, int t, float v) {
    __nv_bfloat16 h = __float2bfloat16_rn(v);
    __nv_bfloat16 lo = __float2bfloat16_rn(v - __bfloat162float(h));
    b[t] = h;
    b[t + 16384] = lo;
}

__global__ void pack_all(const float* __restrict__ ew1, const float* __restrict__ nw1,
                         const float* __restrict__ ew2, const float* __restrict__ nw2,
                         const float* __restrict__ new2, const float* __restrict__ eew2,
                         const float* __restrict__ ndw1) {
    int i = blockIdx.x * 256 + threadIdx.x;
    int m = i >> 14, t = i & 16383;
    int n = t >> 7, k = t & 127;
    const float* src;
    __nv_bfloat16* dst;
    if (m < 24) {
        int l = m / 3, j = m - l * 3;
        src = ew1 + (size_t)m * 16384;
        dst = (j == 0 ? g_wsrc : j == 1 ? g_wdst : g_we) + (size_t)l * 32768;
    } else if (m < 40) {
        int mm = m - 24, l = mm >> 1, j = mm & 1;
        src = nw1 + (size_t)mm * 16384;
        dst = (j ? g_wna : g_wnx) + (size_t)l * 32768;
    } else if (m < 48) {
        src = ew2 + (size_t)(m - 40) * 16384; dst = g_we2 + (size_t)(m - 40) * 32768;
    } else if (m < 56) {
        src = nw2 + (size_t)(m - 48) * 16384; dst = g_wn2 + (size_t)(m - 48) * 32768;
    } else if (m == 56) { src = new2; dst = g_wne2; }
    else if (m == 57)   { src = eew2; dst = g_wee2; }
    else                { src = ndw1; dst = g_wnd1; }
    pack_store(dst, t, src[k * HH + n]);
}

// ===================== counting sort ========================================
__global__ __launch_bounds__(1024, 1) void sort_build(const int* __restrict__ rowi) {
    extern __shared__ int sh[];
    int tid = threadIdx.x;
    for (int i = tid; i < NN; i += 1024) sh[i] = 0;
    __syncthreads();
    for (int i = tid; i < EE; i += 1024) atomicAdd(&sh[rowi[i]], 1);
    __syncthreads();
    int* sums = sh + NN;
    int base = tid * 20;
    int s = 0;
    for (int j = 0; j < 20; j++) {
        int idx = base + j;
        if (idx < NN) s += sh[idx];
    }
    sums[tid] = s;
    __syncthreads();
    for (int off = 1; off < 1024; off <<= 1) {
        int v = (tid >= off) ? sums[tid - off] : 0;
        __syncthreads();
        sums[tid] += v;
        __syncthreads();
    }
    int run = (tid == 0) ? 0 : sums[tid - 1];
    for (int j = 0; j < 20; j++) {
        int idx = base + j;
        if (idx < NN) {
            g_cursor[idx] = run;
            run += sh[idx];
        }
    }
}

__global__ void sort_permute(const int* __restrict__ rowi,
                             const int* __restrict__ coli) {
    int i = blockIdx.x * 256 + threadIdx.x;
    if (i < EE) {
        int r = rowi[i];
        int pos = atomicAdd(&g_cursor[r], 1);
        g_perm[pos] = i;
        g_rowp[pos] = r;
        g_colp[pos] = coli[i];
    }
}

// == persistent edge layer: 2 independent 256-thread groups per CTA =========
__global__ __launch_bounds__(512, 1) void edge_layer_persist(
    int l, const float* __restrict__ b1, const float* __restrict__ b2,
    int nt64, int store_e) {
    extern __shared__ __align__(16) char sm[];
    uint32_t sb = smem_u32(sm);
    int tid = threadIdx.x;
    int grp = tid >> 8, gtid = tid & 255;
    int lid = tid & 31, wid_g = gtid >> 5;
    int wr = wid_g >> 1, wc = wid_g & 1;
    int barG = 1 + grp;
    int barP = 3 + grp * 4 + wr;
    uint32_t ga = (uint32_t)grp * 34816;
    int* rs_s = (int*)(sm + E_RS) + grp * 64;

    copy_w_async<512>(g_we + (size_t)l * 32768, sb, W1_HI);
    copy_w_async<512>(g_we2 + (size_t)l * 32768, sb, W2_HI);
    CP_WAIT();
    __syncthreads();

    int lq = lid >> 2, lr = (lid & 3) * 2;
    int rA = wr * 16 + lq, rB = rA + 8;

    for (int st = blockIdx.x * 2 + grp; st < nt64; st += gridDim.x * 2) {
        int ebase = st * 64;
        BAR_GRP(barG);

        for (int g = gtid; g < 1024; g += 256) {
            int r = g >> 4, cp2 = (g & 15) << 2;
            int er = min(ebase + r, EE - 1);
            uint32_t d = sb + ga + (uint32_t)r * PITCH + (uint32_t)cp2 * 4;
            CP16(d, g_ehi + (size_t)er * 64 + cp2);
            CP16(d + 17408, g_elo + (size_t)er * 64 + cp2);
        }
        if (gtid < 64) rs_s[gtid] = g_rowp[min(ebase + gtid, EE - 1)];

        int eAg = min(ebase + rA, EE - 1), eBg = min(ebase + rB, EE - 1);
        int rowA = g_rowp[eAg], rowB = g_rowp[eBg];
        int colA = g_colp[eAg], colB = g_colp[eBg];

        float acc[8][4];
        {
            const float* xsA = g_xs + (size_t)rowA * HH;
            const float* xdA = g_xd + (size_t)colA * HH;
            const float* xsB = g_xs + (size_t)rowB * HH;
            const float* xdB = g_xd + (size_t)colB * HH;
#pragma unroll
            for (int n = 0; n < 8; n++) {
                int col = wc * 64 + n * 8 + lr;
                float2 bv = *(const float2*)(b1 + col);
                float2 sA = *(const float2*)(xsA + col);
                float2 dA = *(const float2*)(xdA + col);
                float2 sB = *(const float2*)(xsB + col);
                float2 dB = *(const float2*)(xdB + col);
                acc[n][0] = bv.x + sA.x + dA.x;
                acc[n][1] = bv.y + sA.y + dA.y;
                acc[n][2] = bv.x + sB.x + dB.x;
                acc[n][3] = bv.y + sB.y + dB.y;
            }
        }
        CP_WAIT();
        BAR_GRP(barG);

        warp_gemm3_64(sm, ga, W1_HI, wr, wc, lid, acc);
        BAR_PAIR(barP);

#pragma unroll
        for (int n = 0; n < 8; n++) {
            int col = wc * 64 + n * 8 + lr;
            float* c = acc[n];
            uint32_t hi, lo;
            split2(fmaxf(c[0], 0.f), fmaxf(c[1], 0.f), hi, lo);
            *(uint32_t*)(sm + ga + (size_t)rA * PITCH + col * 2) = hi;
            *(uint32_t*)(sm + ga + 17408 + (size_t)rA * PITCH + col * 2) = lo;
            split2(fmaxf(c[2], 0.f), fmaxf(c[3], 0.f), hi, lo);
            *(uint32_t*)(sm + ga + (size_t)rB * PITCH + col * 2) = hi;
            *(uint32_t*)(sm + ga + 17408 + (size_t)rB * PITCH + col * 2) = lo;
        }
        BAR_PAIR(barP);

        ZACC1(acc);
        warp_gemm3_64(sm, ga, W2_HI, wr, wc, lid, acc);
        BAR_GRP(barG);

        {
            int eA = ebase + rA, eB = ebase + rB;
#pragma unroll
            for (int n = 0; n < 8; n++) {
                int col = wc * 64 + n * 8 + lr;
                float2 bv = *(const float2*)(b2 + col);
                float* c = acc[n];
                float vx0 = 0.f, vy0 = 0.f, vx1 = 0.f, vy1 = 0.f;
                if (eA < EE) {
                    vx0 = c[0] + bv.x; vy0 = c[1] + bv.y;
                    if (store_e) {
                        uint32_t hi, lo;
                        split2(vx0, vy0, hi, lo);
                        g_ehi[(size_t)eA * 64 + (col >> 1)] = hi;
                        g_elo[(size_t)eA * 64 + (col >> 1)] = lo;
                    }
                }
                if (eB < EE) {
                    vx1 = c[2] + bv.x; vy1 = c[3] + bv.y;
                    if (store_e) {
                        uint32_t hi, lo;
                        split2(vx1, vy1, hi, lo);
                        g_ehi[(size_t)eB * 64 + (col >> 1)] = hi;
                        g_elo[(size_t)eB * 64 + (col >> 1)] = lo;
                    }
                }
                *(float2*)(sm + ga + (size_t)rA * 544 + col * 4) =
                    make_float2(vx0, vy0);
                *(float2*)(sm + ga + (size_t)rB * 544 + col * 4) =
                    make_float2(vx1, vy1);
            }
        }
        BAR_GRP(barG);

        {
            int cp = (gtid & 63) * 2, q = gtid >> 6;
            int r0 = q * 16, r1 = r0 + 16;
            float s0 = 0.f, s1 = 0.f;
            int prev = rs_s[r0];
            for (int r = r0; r < r1; r++) {
                float2 v = *(const float2*)(sm + ga + (size_t)r * 544 + cp * 4);
                s0 += v.x; s1 += v.y;
                int nxt = (r + 1 < r1) ? rs_s[r + 1] : -2;
                if (nxt != prev) {
                    REDF2(g_agg + (size_t)prev * HH + cp, s0, s1);
                    s0 = 0.f; s1 = 0.f;
                    prev = nxt;
                }
            }
        }
    }
}

// ===== node layer + next-layer xs/xd (or fused decoder on last layer) ======
__global__ __launch_bounds__(512, 1) void node_xsxd(
    int l, const float* __restrict__ b1, const float* __restrict__ b2,
    int do_next, const float* __restrict__ ndb1,
    const float* __restrict__ ndw2, const float* __restrict__ ndb2,
    float* __restrict__ out) {
    extern __shared__ __align__(16) char sm[];
    uint32_t sb = smem_u32(sm);
    int tid = threadIdx.x, lid = tid & 31, wid = tid >> 5;
    int wr = wid >> 1, wc = wid & 1;
    int base = blockIdx.x * 128;
    int lq = lid >> 2, lr = (lid & 3) * 2;
    int rA = wr * 16 + lq, rB = rA + 8;

    copy_w_async<512>(g_wnx + (size_t)l * 32768, sb, W1_HI);
    copy_w_async<512>(g_wna + (size_t)l * 32768, sb, W2_HI);
    load_split_tile_t<512>(g_x, base, NN, sm);
    CP_WAIT();
    __syncthreads();

    float acc[8][4];
    ZACC1(acc);
    warp_gemm3_16(sm, W1_HI, wr, wc, lid, acc);          // x @ wnx
    __syncthreads();                                      // A, W1 free

    copy_w_async<512>(g_wn2 + (size_t)l * 32768, sb, W1_HI);
    load_split_tile_t<512>(g_agg, base, NN, sm);
    __syncthreads();                                      // A(agg) ready
    warp_gemm3_16(sm, W2_HI, wr, wc, lid, acc);          // += agg @ wna
    __syncthreads();                                      // A, W2 free

    if (do_next)
        copy_w_async<512>(g_wsrc + (size_t)(l + 1) * 32768, sb, W2_HI);
    else
        copy_w_async<512>(g_wnd1, sb, W2_HI);
#pragma unroll
    for (int n = 0; n < 8; n++) {
        int col = wc * 64 + n * 8 + lr;
        float2 bv = *(const float2*)(b1 + col);
        float* c = acc[n];
        uint32_t hi, lo;
        split2(fmaxf(c[0] + bv.x, 0.f), fmaxf(c[1] + bv.y, 0.f), hi, lo);
        *(uint32_t*)(sm + A_HI + (size_t)rA * PITCH + col * 2) = hi;
        *(uint32_t*)(sm + A_LO + (size_t)rA * PITCH + col * 2) = lo;
        split2(fmaxf(c[2] + bv.x, 0.f), fmaxf(c[3] + bv.y, 0.f), hi, lo);
        *(uint32_t*)(sm + A_HI + (size_t)rB * PITCH + col * 2) = hi;
        *(uint32_t*)(sm + A_LO + (size_t)rB * PITCH + col * 2) = lo;
    }
    CP_WAIT();
    __syncthreads();

    ZACC1(acc);
    warp_gemm3_16(sm, W1_HI, wr, wc, lid, acc);          // h @ wn2
    __syncthreads();                                      // A(h), W1 free

    if (do_next)
        copy_w_async<512>(g_wdst + (size_t)(l + 1) * 32768, sb, W1_HI);
#pragma unroll
    for (int n = 0; n < 8; n++) {
        int col = wc * 64 + n * 8 + lr;
        float2 bv = *(const float2*)(b2 + col);
        float* c = acc[n];
        uint32_t hi, lo;
        if (base + rA < NN) {
            float* xp = g_x + (size_t)(base + rA) * HH + col;
            float2 xv = *(float2*)xp;
            float vx = c[0] + bv.x + xv.x, vy = c[1] + bv.y + xv.y;
            *(float2*)xp = make_float2(vx, vy);
            split2(vx, vy, hi, lo);
        } else split2(0.f, 0.f, hi, lo);
        *(uint32_t*)(sm + A_HI + (size_t)rA * PITCH + col * 2) = hi;
        *(uint32_t*)(sm + A_LO + (size_t)rA * PITCH + col * 2) = lo;
        if (base + rB < NN) {
            float* xp = g_x + (size_t)(base + rB) * HH + col;
            float2 xv = *(float2*)xp;
            float vx = c[2] + bv.x + xv.x, vy = c[3] + bv.y + xv.y;
            *(float2*)xp = make_float2(vx, vy);
            split2(vx, vy, hi, lo);
        } else split2(0.f, 0.f, hi, lo);
        *(uint32_t*)(sm + A_HI + (size_t)rB * PITCH + col * 2) = hi;
        *(uint32_t*)(sm + A_LO + (size_t)rB * PITCH + col * 2) = lo;
    }
    if (do_next) {
        for (int i = tid; i < 4096; i += 512) {
            int r = i >> 5, c4 = i & 31;
            if (base + r < NN)
                ((float4*)g_agg)[(size_t)(base + r) * 32 + c4] =
                    make_float4(0.f, 0.f, 0.f, 0.f);
        }
    }
    CP_WAIT();
    __syncthreads();   // A(x_new) complete; prefetched W landed

    if (do_next) {
        ZACC1(acc);
        warp_gemm3_16(sm, W2_HI, wr, wc, lid, acc);      // x_new @ wsrc
#pragma unroll
        for (int n = 0; n < 8; n++) {
            int col = wc * 64 + n * 8 + lr;
            float* c = acc[n];
            if (base + rA < NN)
                *(float2*)(g_xs + (size_t)(base + rA) * HH + col) =
                    make_float2(c[0], c[1]);
            if (base + rB < NN)
                *(float2*)(g_xs + (size_t)(base + rB) * HH + col) =
                    make_float2(c[2], c[3]);
        }

        ZACC1(acc);
        warp_gemm3_16(sm, W1_HI, wr, wc, lid, acc);      // x_new @ wdst
#pragma unroll
        for (int n = 0; n < 8; n++) {
            int col = wc * 64 + n * 8 + lr;
            float* c = acc[n];
            if (base + rA < NN)
                *(float2*)(g_xd + (size_t)(base + rA) * HH + col) =
                    make_float2(c[0], c[1]);
            if (base + rB < NN)
                *(float2*)(g_xd + (size_t)(base + rB) * HH + col) =
                    make_float2(c[2], c[3]);
        }
        return;
    }

    // ---- fused decoder (last layer): out = relu(x_new@nd_w1+b1)@nd_w2+b2 ---
    ZACC1(acc);
    warp_gemm3_16(sm, W2_HI, wr, wc, lid, acc);          // x_new @ nd_w1
    __syncthreads();   // all warps done reading A(x_new) before f32 overwrite

#pragma unroll
    for (int n = 0; n < 8; n++) {
        int col = wc * 64 + n * 8 + lr;
        float2 bv = *(const float2*)(ndb1 + col);
        float* c = acc[n];
        *(float2*)(sm + (size_t)rA * 544 + col * 4) =
            make_float2(fmaxf(c[0] + bv.x, 0.f), fmaxf(c[1] + bv.y, 0.f));
        *(float2*)(sm + (size_t)rB * 544 + col * 4) =
            make_float2(fmaxf(c[2] + bv.x, 0.f), fmaxf(c[3] + bv.y, 0.f));
    }
    __syncthreads();

    if (tid < 384) {
        int r = tid / 3, c = tid - r * 3;
        float s = ndb2[c];
#pragma unroll 4
        for (int k = 0; k < HH; k++)
            s += *(const float*)(sm + (size_t)r * 544 + k * 4) * ndw2[k * 3 + c];
        int nr = base + r;
        if (nr < NN) out[nr * 3 + c] = s;
    }
}

// ====== node encoder fused with xs/xd projection of layer 0 + agg zero =====
__global__ __launch_bounds__(256, 1) void encoder_node_fused(
    const float* __restrict__ in, const float* __restrict__ w1,
    const float* __restrict__ b1, const float* __restrict__ b2) {
    extern __shared__ __align__(16) char sm[];
    int tid = threadIdx.x, lid = tid & 31, wid = tid >> 5;
    int wr = wid >> 1, wc = wid & 1;
    int base = blockIdx.x * 128;
    int lq = lid >> 2, lr = (lid & 3) * 2;

    for (int g = tid; g < 2048; g += 256) {
        int r = g >> 4, c8 = (g & 15) << 3;
        int rr = min(base + r, NN - 1);
        float vin[6];
#pragma unroll
        for (int k = 0; k < 6; k++) vin[k] = in[(size_t)rr * 6 + k];
        float h[8];
#pragma unroll
        for (int c = 0; c < 8; c++) {
            int cc = c8 + c;
            float s = b1[cc];
#pragma unroll
            for (int k = 0; k < 6; k++) s += vin[k] * w1[k * HH + cc];
            h[c] = fmaxf(s, 0.f);
        }
        uint32_t hv[4], lv[4];
        split2(h[0], h[1], hv[0], lv[0]);
        split2(h[2], h[3], hv[1], lv[1]);
        split2(h[4], h[5], hv[2], lv[2]);
        split2(h[6], h[7], hv[3], lv[3]);
        char* dst = sm + (size_t)r * PITCH + c8 * 2;
        *(uint4*)(dst + A_HI) = make_uint4(hv[0], hv[1], hv[2], hv[3]);
        *(uint4*)(dst + A_LO) = make_uint4(lv[0], lv[1], lv[2], lv[3]);
    }
    copy_w(g_wne2, sm, B_HI);
    __syncthreads();

    float acc[2][8][4];
    ZACC(acc);
    warp_gemm3(sm, B_HI, wr, wc, lid, acc);
    __syncthreads();

#pragma unroll
    for (int m = 0; m < 2; m++) {
        int rA = wr * 32 + m * 16 + lq, rB = rA + 8;
#pragma unroll
        for (int n = 0; n < 8; n++) {
            int col = wc * 64 + n * 8 + lr;
            float2 bv = *(const float2*)(b2 + col);
            float* c = acc[m][n];
            float vx0 = c[0] + bv.x, vy0 = c[1] + bv.y;
            float vx1 = c[2] + bv.x, vy1 = c[3] + bv.y;
            uint32_t hi, lo;
            if (base + rA < NN)
                *(float2*)(g_x + (size_t)(base + rA) * HH + col) =
                    make_float2(vx0, vy0);
            split2(vx0, vy0, hi, lo);
            *(uint32_t*)(sm + A_HI + (size_t)rA * PITCH + col * 2) = hi;
            *(uint32_t*)(sm + A_LO + (size_t)rA * PITCH + col * 2) = lo;
            if (base + rB < NN)
                *(float2*)(g_x + (size_t)(base + rB) * HH + col) =
                    make_float2(vx1, vy1);
            split2(vx1, vy1, hi, lo);
            *(uint32_t*)(sm + A_HI + (size_t)rB * PITCH + col * 2) = hi;
            *(uint32_t*)(sm + A_LO + (size_t)rB * PITCH + col * 2) = lo;
        }
    }
    for (int i = tid; i < 4096; i += 256) {
        int r = i >> 5, c4 = i & 31;
        if (base + r < NN)
            ((float4*)g_agg)[(size_t)(base + r) * 32 + c4] =
                make_float4(0.f, 0.f, 0.f, 0.f);
    }
    copy_w(g_wsrc, sm, B_HI);
    __syncthreads();
    ZACC(acc);
    warp_gemm3(sm, B_HI, wr, wc, lid, acc);
#pragma unroll
    for (int m = 0; m < 2; m++) {
        int rA = wr * 32 + m * 16 + lq, rB = rA + 8;
#pragma unroll
        for (int n = 0; n < 8; n++) {
            int col = wc * 64 + n * 8 + lr;
            float* c = acc[m][n];
            if (base + rA < NN)
                *(float2*)(g_xs + (size_t)(base + rA) * HH + col) =
                    make_float2(c[0], c[1]);
            if (base + rB < NN)
                *(float2*)(g_xs + (size_t)(base + rB) * HH + col) =
                    make_float2(c[2], c[3]);
        }
    }
    __syncthreads();
    copy_w(g_wdst, sm, B_HI);
    __syncthreads();
    ZACC(acc);
    warp_gemm3(sm, B_HI, wr, wc, lid, acc);
#pragma unroll
    for (int m = 0; m < 2; m++) {
        int rA = wr * 32 + m * 16 + lq, rB = rA + 8;
#pragma unroll
        for (int n = 0; n < 8; n++) {
            int col = wc * 64 + n * 8 + lr;
            float* c = acc[m][n];
            if (base + rA < NN)
                *(float2*)(g_xd + (size_t)(base + rA) * HH + col) =
                    make_float2(c[0], c[1]);
            if (base + rB < NN)
                *(float2*)(g_xd + (size_t)(base + rB) * HH + col) =
                    make_float2(c[2], c[3]);
        }
    }
}

// ==== edge encoder: 2 independent 256-thread groups, W shared, PERMUTED ====
__global__ __launch_bounds__(512, 1) void encoder_edge(
    const float* __restrict__ in, const float* __restrict__ w1,
    const float* __restrict__ b1, const float* __restrict__ b2, int nt64) {
    extern __shared__ __align__(16) char sm[];
    uint32_t sb = smem_u32(sm);
    int tid = threadIdx.x;
    int grp = tid >> 8, gtid = tid & 255;
    int lid = tid & 31, wid_g = gtid >> 5;
    int wr = wid_g >> 1, wc = wid_g & 1;
    int barG = 1 + grp;
    uint32_t ga = (uint32_t)grp * 34816;

    copy_w_async<512>(g_wee2, sb, B_HI);
    CP_WAIT();
    __syncthreads();
    int lq = lid >> 2, lr = (lid & 3) * 2;
    int rA = wr * 16 + lq, rB = rA + 8;

    for (int st = blockIdx.x * 2 + grp; st < nt64; st += gridDim.x * 2) {
        int base = st * 64;
        BAR_GRP(barG);
        for (int g = gtid; g < 1024; g += 256) {
            int r = g >> 4, c8 = (g & 15) << 3;
            int rr = min(base + r, EE - 1);
            int src = g_perm[rr];
            float vin[3];
#pragma unroll
            for (int k = 0; k < 3; k++) vin[k] = in[(size_t)src * 3 + k];
            float h[8];
#pragma unroll
            for (int c = 0; c < 8; c++) {
                int cc = c8 + c;
                float s = b1[cc];
#pragma unroll
                for (int k = 0; k < 3; k++) s += vin[k] * w1[k * HH + cc];
                h[c] = fmaxf(s, 0.f);
            }
            uint32_t hv[4], lv[4];
            split2(h[0], h[1], hv[0], lv[0]);
            split2(h[2], h[3], hv[1], lv[1]);
            split2(h[4], h[5], hv[2], lv[2]);
            split2(h[6], h[7], hv[3], lv[3]);
            char* dst = sm + ga + (size_t)r * PITCH + c8 * 2;
            *(uint4*)(dst) = make_uint4(hv[0], hv[1], hv[2], hv[3]);
            *(uint4*)(dst + 17408) = make_uint4(lv[0], lv[1], lv[2], lv[3]);
        }
        BAR_GRP(barG);

        float acc[8][4];
        ZACC1(acc);
        warp_gemm3_64(sm, ga, B_HI, wr, wc, lid, acc);

#pragma unroll
        for (int n = 0; n < 8; n++) {
            int col = wc * 64 + n * 8 + lr;
            float2 bv = *(const float2*)(b2 + col);
            float* c = acc[n];
            uint32_t hi, lo;
            if (base + rA < EE) {
                split2(c[0] + bv.x, c[1] + bv.y, hi, lo);
                g_ehi[(size_t)(base + rA) * 64 + (col >> 1)] = hi;
                g_elo[(size_t)(base + rA) * 64 + (col >> 1)] = lo;
            }
            if (base + rB < EE) {
                split2(c[2] + bv.x, c[3] + bv.y, hi, lo);
                g_ehi[(size_t)(base + rB) * 64 + (col >> 1)] = hi;
                g_elo[(size_t)(base + rB) * 64 + (col >> 1)] = lo;
            }
        }
    }
}

// ============================================================================
extern "C" void kernel_launch(void* const* d_in, const int* in_sizes, int n_in,
                              void* d_out, int out_size) {
    const float* x_in    = (const float*)d_in[0];
    const float* eattr   = (const float*)d_in[1];
    const float* ne_w1   = (const float*)d_in[2];
    const float* ne_b1   = (const float*)d_in[3];
    const float* ne_w2   = (const float*)d_in[4];
    const float* ne_b2   = (const float*)d_in[5];
    const float* ee_w1   = (const float*)d_in[6];
    const float* ee_b1   = (const float*)d_in[7];
    const float* ee_w2   = (const float*)d_in[8];
    const float* ee_b2   = (const float*)d_in[9];
    const float* edge_w1 = (const float*)d_in[10];
    const float* edge_b1 = (const float*)d_in[11];
    const float* edge_w2 = (const float*)d_in[12];
    const float* edge_b2 = (const float*)d_in[13];
    const float* node_w1 = (const float*)d_in[14];
    const float* node_b1 = (const float*)d_in[15];
    const float* node_w2 = (const float*)d_in[16];
    const float* node_b2 = (const float*)d_in[17];
    const float* nd_w1   = (const float*)d_in[18];
    const float* nd_b1   = (const float*)d_in[19];
    const float* nd_w2   = (const float*)d_in[20];
    const float* nd_b2   = (const float*)d_in[21];
    const int*   eidx    = (const int*)d_in[22];
    const int*   rowi    = eidx;
    const int*   coli    = eidx + EE;

    cudaFuncSetAttribute(edge_layer_persist,
                         cudaFuncAttributeMaxDynamicSharedMemorySize, E_SMEM);
    cudaFuncSetAttribute(node_xsxd,
                         cudaFuncAttributeMaxDynamicSharedMemorySize, N_SMEM);
    cudaFuncSetAttribute(encoder_node_fused,
                         cudaFuncAttributeMaxDynamicSharedMemorySize, G_SMEM);
    cudaFuncSetAttribute(encoder_edge,
                         cudaFuncAttributeMaxDynamicSharedMemorySize, G_SMEM);
    cudaFuncSetAttribute(sort_build,
                         cudaFuncAttributeMaxDynamicSharedMemorySize,
                         (NN + 1024) * 4);

    const int TB_N = (NN + 127) / 128;   // 157
    const int NT64E = (EE + 63) / 64;    // 4688

    pack_all<<<59 * 64, 256>>>(edge_w1, node_w1, edge_w2, node_w2,
                               ne_w2, ee_w2, nd_w1);
    sort_build<<<1, 1024, (NN + 1024) * 4>>>(rowi);
    sort_permute<<<(EE + 255) / 256, 256>>>(rowi, coli);

    encoder_edge<<<NSM, 512, G_SMEM>>>(eattr, ee_w1, ee_b1, ee_b2, NT64E);
    encoder_node_fused<<<TB_N, 256, G_SMEM>>>(x_in, ne_w1, ne_b1, ne_b2);

    for (int l = 0; l < LL; l++) {
        edge_layer_persist<<<NSM, 512, E_SMEM>>>(l, edge_b1 + l * HH,
                                                 edge_b2 + l * HH,
                                                 NT64E, l < LL - 1 ? 1 : 0);
        node_xsxd<<<TB_N, 512, N_SMEM>>>(l, node_b1 + l * HH,
                                         node_b2 + l * HH,
                                         l < LL - 1 ? 1 : 0,
                                         nd_b1, nd_w2, nd_b2, (float*)d_out);
    }
}

// round 17
// speedup vs baseline: 1.0572x; 1.0456x over previous
#include <cuda_runtime.h>
#include <cuda_bf16.h>
#include <cstdint>

#define NN 20000
#define EE 300000
#define HH 128
#define LL 8
#define PITCH 272
#define NSM 148

#define A_HI 0
#define A_LO 34816
#define B_HI 69632
#define G_SMEM 140288
#define W1_HI 69632
#define W2_HI 139264
#define E_RS  208896
#define E_SMEM 209408
// node 64-row kernel: A(hi,lo) 0..34816, W(hi,lo) 34816..104448
#define NW_HI 34816
#define N64_SMEM 104448

#define BAR_PAIR(id) asm volatile("bar.sync %0, 64;" :: "r"(id) : "memory")
#define BAR_GRP(id)  asm volatile("bar.sync %0, 256;" :: "r"(id) : "memory")

// ============================ scratch globals ===============================
__device__ __align__(16) float g_x  [NN * HH];
__device__ __align__(16) float g_xs [NN * HH];
__device__ __align__(16) float g_xd [NN * HH];
__device__ __align__(16) float g_agg[NN * HH];
__device__ __align__(16) uint32_t g_ehi[(size_t)EE * 64];
__device__ __align__(16) uint32_t g_elo[(size_t)EE * 64];
__device__ int g_cursor[NN];
__device__ int g_perm[EE];
__device__ int g_rowp[EE];
__device__ int g_colp[EE];

__device__ __align__(16) __nv_bfloat16 g_wsrc[LL * 32768];
__device__ __align__(16) __nv_bfloat16 g_wdst[LL * 32768];
__device__ __align__(16) __nv_bfloat16 g_we  [LL * 32768];
__device__ __align__(16) __nv_bfloat16 g_we2 [LL * 32768];
__device__ __align__(16) __nv_bfloat16 g_wnx [LL * 32768];
__device__ __align__(16) __nv_bfloat16 g_wna [LL * 32768];
__device__ __align__(16) __nv_bfloat16 g_wn2 [LL * 32768];
__device__ __align__(16) __nv_bfloat16 g_wne2[32768];
__device__ __align__(16) __nv_bfloat16 g_wee2[32768];
__device__ __align__(16) __nv_bfloat16 g_wnd1[32768];

// ============================ helpers =======================================
__device__ __forceinline__ uint32_t smem_u32(const void* p) {
    uint32_t a;
    asm("{ .reg .u64 t; cvta.to.shared.u64 t, %1; cvt.u32.u64 %0, t; }"
        : "=r"(a) : "l"(p));
    return a;
}
__device__ __forceinline__ void ldsm4(uint32_t addr, uint32_t r[4]) {
    asm volatile("ldmatrix.sync.aligned.m8n8.x4.shared.b16 {%0,%1,%2,%3}, [%4];"
                 : "=r"(r[0]), "=r"(r[1]), "=r"(r[2]), "=r"(r[3]) : "r"(addr));
}
__device__ __forceinline__ void mma16816(float c[4], const uint32_t a[4],
                                         const uint32_t* b) {
    asm volatile("mma.sync.aligned.m16n8k16.row.col.f32.bf16.bf16.f32 "
                 "{%0,%1,%2,%3}, {%4,%5,%6,%7}, {%8,%9}, {%0,%1,%2,%3};"
                 : "+f"(c[0]), "+f"(c[1]), "+f"(c[2]), "+f"(c[3])
                 : "r"(a[0]), "r"(a[1]), "r"(a[2]), "r"(a[3]),
                   "r"(b[0]), "r"(b[1]));
}
#define CP16(dst, src) \
    asm volatile("cp.async.cg.shared.global [%0], [%1], 16;" \
                 :: "r"(dst), "l"(src) : "memory")
#define CP_WAIT() \
    asm volatile("cp.async.commit_group;\n\tcp.async.wait_group 0;" ::: "memory")
#define REDF2(ptr, v0, v1) \
    asm volatile("red.global.add.v2.f32 [%0], {%1, %2};" \
                 :: "l"(ptr), "f"(v0), "f"(v1) : "memory")

__device__ __forceinline__ void split2(float a, float b, uint32_t& hi, uint32_t& lo) {
    asm("cvt.rn.bf16x2.f32 %0, %1, %2;" : "=r"(hi) : "f"(b), "f"(a));
    float ah = __uint_as_float(hi << 16);
    float bh = __uint_as_float(hi & 0xFFFF0000u);
    asm("cvt.rn.bf16x2.f32 %0, %1, %2;" : "=r"(lo) : "f"(b - bh), "f"(a - ah));
}

// 3-term GEMM, warp tile 32x64 (256-thread, 128-row A); A lo at +34816
__device__ __forceinline__ void warp_gemm3(const char* sm, uint32_t b_off,
                                           int wr, int wc, int lid,
                                           float acc[2][8][4]) {
    uint32_t sb = smem_u32(sm);
    uint32_t a_base = sb + A_HI + (uint32_t)(wr * 32 + (lid & 15)) * PITCH +
                      (uint32_t)((lid >> 4) * 8) * 2;
    uint32_t b_base = sb + b_off +
        (uint32_t)(wc * 64 + ((lid >> 4) & 1) * 8 + (lid & 7)) * PITCH +
        (uint32_t)(((lid >> 3) & 1) * 8) * 2;
#pragma unroll
    for (int ks = 0; ks < 8; ks++) {
        uint32_t ko = ks * 32;
        uint32_t Ah[2][4], Al[2][4], Bh[4][4], Bl[4][4];
        ldsm4(a_base + ko, Ah[0]);
        ldsm4(a_base + 16 * PITCH + ko, Ah[1]);
        ldsm4(a_base + 34816 + ko, Al[0]);
        ldsm4(a_base + 34816 + 16 * PITCH + ko, Al[1]);
#pragma unroll
        for (int g = 0; g < 4; g++) {
            ldsm4(b_base + g * 16 * PITCH + ko, Bh[g]);
            ldsm4(b_base + 34816 + g * 16 * PITCH + ko, Bl[g]);
        }
#pragma unroll
        for (int m = 0; m < 2; m++)
#pragma unroll
            for (int g = 0; g < 4; g++)
#pragma unroll
                for (int s = 0; s < 2; s++) {
                    float* c = acc[m][g * 2 + s];
                    mma16816(c, Ah[m], &Bh[g][2 * s]);
                    mma16816(c, Al[m], &Bh[g][2 * s]);
                    mma16816(c, Ah[m], &Bl[g][2 * s]);
                }
    }
}

// 3-term GEMM, warp tile 16x64, 64-row A region at a_off (lo at +17408),
// weight at b_off (lo at +34816)
__device__ __forceinline__ void warp_gemm3_64(const char* sm, uint32_t a_off,
                                              uint32_t b_off, int wr, int wc,
                                              int lid, float acc[8][4]) {
    uint32_t sb = smem_u32(sm);
    uint32_t a_base = sb + a_off + (uint32_t)(wr * 16 + (lid & 15)) * PITCH +
                      (uint32_t)((lid >> 4) * 8) * 2;
    uint32_t b_base = sb + b_off +
        (uint32_t)(wc * 64 + ((lid >> 4) & 1) * 8 + (lid & 7)) * PITCH +
        (uint32_t)(((lid >> 3) & 1) * 8) * 2;
#pragma unroll
    for (int ks = 0; ks < 8; ks++) {
        uint32_t ko = ks * 32;
        uint32_t Ah[4], Al[4];
        ldsm4(a_base + ko, Ah);
        ldsm4(a_base + 17408 + ko, Al);
#pragma unroll
        for (int g = 0; g < 4; g++) {
            uint32_t Bh[4], Bl[4];
            ldsm4(b_base + g * 16 * PITCH + ko, Bh);
            ldsm4(b_base + 34816 + g * 16 * PITCH + ko, Bl);
#pragma unroll
            for (int s = 0; s < 2; s++) {
                float* c = acc[g * 2 + s];
                mma16816(c, Ah, &Bh[2 * s]);
                mma16816(c, Al, &Bh[2 * s]);
                mma16816(c, Ah, &Bl[2 * s]);
            }
        }
    }
}

#define ZACC(acc)                                   \
    _Pragma("unroll") for (int _m = 0; _m < 2; _m++) \
    _Pragma("unroll") for (int _n = 0; _n < 8; _n++) \
    _Pragma("unroll") for (int _q = 0; _q < 4; _q++) acc[_m][_n][_q] = 0.f;
#define ZACC1(acc)                                  \
    _Pragma("unroll") for (int _n = 0; _n < 8; _n++) \
    _Pragma("unroll") for (int _q = 0; _q < 4; _q++) acc[_n][_q] = 0.f;

template <int NT>
__device__ __forceinline__ void load_split_tile_t(const float* __restrict__ src,
                                                  int base, int maxr, char* sm) {
    for (int g = threadIdx.x; g < 2048; g += NT) {
        int r = g >> 4, c8 = (g & 15) << 3;
        int rr = min(base + r, maxr - 1);
        const float* p = src + (size_t)rr * HH + c8;
        float4 v0 = *(const float4*)p;
        float4 v1 = *(const float4*)(p + 4);
        uint32_t h0, l0, h1, l1, h2, l2, h3, l3;
        split2(v0.x, v0.y, h0, l0); split2(v0.z, v0.w, h1, l1);
        split2(v1.x, v1.y, h2, l2); split2(v1.z, v1.w, h3, l3);
        char* dst = sm + (size_t)r * PITCH + c8 * 2;
        *(uint4*)(dst + A_HI) = make_uint4(h0, h1, h2, h3);
        *(uint4*)(dst + A_LO) = make_uint4(l0, l1, l2, l3);
    }
}

// load 64-row f32 tile -> bf16 hi/lo into buffer at ga (lo at +17408)
__device__ __forceinline__ void load_split_64(const float* __restrict__ src,
                                              int base, int maxr, char* sm,
                                              uint32_t ga, int gtid) {
    for (int g = gtid; g < 1024; g += 256) {
        int r = g >> 4, c8 = (g & 15) << 3;
        int rr = min(base + r, maxr - 1);
        const float* p = src + (size_t)rr * HH + c8;
        float4 v0 = *(const float4*)p;
        float4 v1 = *(const float4*)(p + 4);
        uint32_t h0, l0, h1, l1, h2, l2, h3, l3;
        split2(v0.x, v0.y, h0, l0); split2(v0.z, v0.w, h1, l1);
        split2(v1.x, v1.y, h2, l2); split2(v1.z, v1.w, h3, l3);
        char* dst = sm + ga + (size_t)r * PITCH + c8 * 2;
        *(uint4*)(dst) = make_uint4(h0, h1, h2, h3);
        *(uint4*)(dst + 17408) = make_uint4(l0, l1, l2, l3);
    }
}

__device__ __forceinline__ void copy_w(const __nv_bfloat16* __restrict__ w,
                                       char* sm, uint32_t off_hi) {
    const uint4* s = (const uint4*)w;
    for (int i = threadIdx.x; i < 2048; i += 256) {
        int r = i >> 4, c = i & 15;
        char* dst = sm + off_hi + (size_t)r * PITCH + c * 16;
        *(uint4*)(dst) = s[i];
        *(uint4*)(dst + 34816) = s[i + 2048];
    }
}

template <int NT>
__device__ __forceinline__ void copy_w_async(const __nv_bfloat16* __restrict__ w,
                                             uint32_t sb, uint32_t off_hi) {
    const uint4* s = (const uint4*)w;
    for (int i = threadIdx.x; i < 2048; i += NT) {
        int r = i >> 4, c = i & 15;
        uint32_t dst = sb + off_hi + (uint32_t)r * PITCH + (uint32_t)c * 16;
        CP16(dst, s + i);
        CP16(dst + 34816, s + i + 2048);
    }
}

// ============================ pack kernel ===================================
__device__ __forceinline__ void pack_store(__nv_bfloat16* b, int t, float v) {
    __nv_bfloat16 h = __float2bfloat16_rn(v);
    __nv_bfloat16 lo = __float2bfloat16_rn(v - __bfloat162float(h));
    b[t] = h;
    b[t + 16384] = lo;
}

__global__ void pack_all(const float* __restrict__ ew1, const float* __restrict__ nw1,
                         const float* __restrict__ ew2, const float* __restrict__ nw2,
                         const float* __restrict__ new2, const float* __restrict__ eew2,
                         const float* __restrict__ ndw1) {
    int i = blockIdx.x * 256 + threadIdx.x;
    int m = i >> 14, t = i & 16383;
    int n = t >> 7, k = t & 127;
    const float* src;
    __nv_bfloat16* dst;
    if (m < 24) {
        int l = m / 3, j = m - l * 3;
        src = ew1 + (size_t)m * 16384;
        dst = (j == 0 ? g_wsrc : j == 1 ? g_wdst : g_we) + (size_t)l * 32768;
    } else if (m < 40) {
        int mm = m - 24, l = mm >> 1, j = mm & 1;
        src = nw1 + (size_t)mm * 16384;
        dst = (j ? g_wna : g_wnx) + (size_t)l * 32768;
    } else if (m < 48) {
        src = ew2 + (size_t)(m - 40) * 16384; dst = g_we2 + (size_t)(m - 40) * 32768;
    } else if (m < 56) {
        src = nw2 + (size_t)(m - 48) * 16384; dst = g_wn2 + (size_t)(m - 48) * 32768;
    } else if (m == 56) { src = new2; dst = g_wne2; }
    else if (m == 57)   { src = eew2; dst = g_wee2; }
    else                { src = ndw1; dst = g_wnd1; }
    pack_store(dst, t, src[k * HH + n]);
}

// ===================== counting sort ========================================
__global__ __launch_bounds__(1024, 1) void sort_build(const int* __restrict__ rowi) {
    extern __shared__ int sh[];
    int tid = threadIdx.x;
    for (int i = tid; i < NN; i += 1024) sh[i] = 0;
    __syncthreads();
    for (int i = tid; i < EE; i += 1024) atomicAdd(&sh[rowi[i]], 1);
    __syncthreads();
    int* sums = sh + NN;
    int base = tid * 20;
    int s = 0;
    for (int j = 0; j < 20; j++) {
        int idx = base + j;
        if (idx < NN) s += sh[idx];
    }
    sums[tid] = s;
    __syncthreads();
    for (int off = 1; off < 1024; off <<= 1) {
        int v = (tid >= off) ? sums[tid - off] : 0;
        __syncthreads();
        sums[tid] += v;
        __syncthreads();
    }
    int run = (tid == 0) ? 0 : sums[tid - 1];
    for (int j = 0; j < 20; j++) {
        int idx = base + j;
        if (idx < NN) {
            g_cursor[idx] = run;
            run += sh[idx];
        }
    }
}

__global__ void sort_permute(const int* __restrict__ rowi,
                             const int* __restrict__ coli) {
    int i = blockIdx.x * 256 + threadIdx.x;
    if (i < EE) {
        int r = rowi[i];
        int pos = atomicAdd(&g_cursor[r], 1);
        g_perm[pos] = i;
        g_rowp[pos] = r;
        g_colp[pos] = coli[i];
    }
}

// == persistent edge layer: 2 independent 256-thread groups per CTA =========
__global__ __launch_bounds__(512, 1) void edge_layer_persist(
    int l, const float* __restrict__ b1, const float* __restrict__ b2,
    int nt64, int store_e) {
    extern __shared__ __align__(16) char sm[];
    uint32_t sb = smem_u32(sm);
    int tid = threadIdx.x;
    int grp = tid >> 8, gtid = tid & 255;
    int lid = tid & 31, wid_g = gtid >> 5;
    int wr = wid_g >> 1, wc = wid_g & 1;
    int barG = 1 + grp;
    int barP = 3 + grp * 4 + wr;
    uint32_t ga = (uint32_t)grp * 34816;
    int* rs_s = (int*)(sm + E_RS) + grp * 64;

    copy_w_async<512>(g_we + (size_t)l * 32768, sb, W1_HI);
    copy_w_async<512>(g_we2 + (size_t)l * 32768, sb, W2_HI);
    CP_WAIT();
    __syncthreads();

    int lq = lid >> 2, lr = (lid & 3) * 2;
    int rA = wr * 16 + lq, rB = rA + 8;

    for (int st = blockIdx.x * 2 + grp; st < nt64; st += gridDim.x * 2) {
        int ebase = st * 64;
        BAR_GRP(barG);

        for (int g = gtid; g < 1024; g += 256) {
            int r = g >> 4, cp2 = (g & 15) << 2;
            int er = min(ebase + r, EE - 1);
            uint32_t d = sb + ga + (uint32_t)r * PITCH + (uint32_t)cp2 * 4;
            CP16(d, g_ehi + (size_t)er * 64 + cp2);
            CP16(d + 17408, g_elo + (size_t)er * 64 + cp2);
        }
        if (gtid < 64) rs_s[gtid] = g_rowp[min(ebase + gtid, EE - 1)];

        int eAg = min(ebase + rA, EE - 1), eBg = min(ebase + rB, EE - 1);
        int rowA = g_rowp[eAg], rowB = g_rowp[eBg];
        int colA = g_colp[eAg], colB = g_colp[eBg];

        float acc[8][4];
        {
            const float* xsA = g_xs + (size_t)rowA * HH;
            const float* xdA = g_xd + (size_t)colA * HH;
            const float* xsB = g_xs + (size_t)rowB * HH;
            const float* xdB = g_xd + (size_t)colB * HH;
#pragma unroll
            for (int n = 0; n < 8; n++) {
                int col = wc * 64 + n * 8 + lr;
                float2 bv = *(const float2*)(b1 + col);
                float2 sA = *(const float2*)(xsA + col);
                float2 dA = *(const float2*)(xdA + col);
                float2 sB = *(const float2*)(xsB + col);
                float2 dB = *(const float2*)(xdB + col);
                acc[n][0] = bv.x + sA.x + dA.x;
                acc[n][1] = bv.y + sA.y + dA.y;
                acc[n][2] = bv.x + sB.x + dB.x;
                acc[n][3] = bv.y + sB.y + dB.y;
            }
        }
        CP_WAIT();
        BAR_GRP(barG);

        warp_gemm3_64(sm, ga, W1_HI, wr, wc, lid, acc);
        BAR_PAIR(barP);

#pragma unroll
        for (int n = 0; n < 8; n++) {
            int col = wc * 64 + n * 8 + lr;
            float* c = acc[n];
            uint32_t hi, lo;
            split2(fmaxf(c[0], 0.f), fmaxf(c[1], 0.f), hi, lo);
            *(uint32_t*)(sm + ga + (size_t)rA * PITCH + col * 2) = hi;
            *(uint32_t*)(sm + ga + 17408 + (size_t)rA * PITCH + col * 2) = lo;
            split2(fmaxf(c[2], 0.f), fmaxf(c[3], 0.f), hi, lo);
            *(uint32_t*)(sm + ga + (size_t)rB * PITCH + col * 2) = hi;
            *(uint32_t*)(sm + ga + 17408 + (size_t)rB * PITCH + col * 2) = lo;
        }
        BAR_PAIR(barP);

        ZACC1(acc);
        warp_gemm3_64(sm, ga, W2_HI, wr, wc, lid, acc);
        BAR_GRP(barG);

        {
            int eA = ebase + rA, eB = ebase + rB;
#pragma unroll
            for (int n = 0; n < 8; n++) {
                int col = wc * 64 + n * 8 + lr;
                float2 bv = *(const float2*)(b2 + col);
                float* c = acc[n];
                float vx0 = 0.f, vy0 = 0.f, vx1 = 0.f, vy1 = 0.f;
                if (eA < EE) {
                    vx0 = c[0] + bv.x; vy0 = c[1] + bv.y;
                    if (store_e) {
                        uint32_t hi, lo;
                        split2(vx0, vy0, hi, lo);
                        g_ehi[(size_t)eA * 64 + (col >> 1)] = hi;
                        g_elo[(size_t)eA * 64 + (col >> 1)] = lo;
                    }
                }
                if (eB < EE) {
                    vx1 = c[2] + bv.x; vy1 = c[3] + bv.y;
                    if (store_e) {
                        uint32_t hi, lo;
                        split2(vx1, vy1, hi, lo);
                        g_ehi[(size_t)eB * 64 + (col >> 1)] = hi;
                        g_elo[(size_t)eB * 64 + (col >> 1)] = lo;
                    }
                }
                *(float2*)(sm + ga + (size_t)rA * 544 + col * 4) =
                    make_float2(vx0, vy0);
                *(float2*)(sm + ga + (size_t)rB * 544 + col * 4) =
                    make_float2(vx1, vy1);
            }
        }
        BAR_GRP(barG);

        {
            int cp = (gtid & 63) * 2, q = gtid >> 6;
            int r0 = q * 16, r1 = r0 + 16;
            float s0 = 0.f, s1 = 0.f;
            int prev = rs_s[r0];
            for (int r = r0; r < r1; r++) {
                float2 v = *(const float2*)(sm + ga + (size_t)r * 544 + cp * 4);
                s0 += v.x; s1 += v.y;
                int nxt = (r + 1 < r1) ? rs_s[r + 1] : -2;
                if (nxt != prev) {
                    REDF2(g_agg + (size_t)prev * HH + cp, s0, s1);
                    s0 = 0.f; s1 = 0.f;
                    prev = nxt;
                }
            }
        }
    }
}

// === node layer + next xs/xd (or fused decoder): 64-row tiles, 2 CTAs/SM ===
__global__ __launch_bounds__(256, 2) void node_xsxd64(
    int l, const float* __restrict__ b1, const float* __restrict__ b2,
    int do_next, const float* __restrict__ ndb1,
    const float* __restrict__ ndw2, const float* __restrict__ ndb2,
    float* __restrict__ out) {
    extern __shared__ __align__(16) char sm[];
    uint32_t sb = smem_u32(sm);
    int tid = threadIdx.x, lid = tid & 31, wid = tid >> 5;
    int wr = wid >> 1, wc = wid & 1;
    int base = blockIdx.x * 64;
    int lq = lid >> 2, lr = (lid & 3) * 2;
    int rA = wr * 16 + lq, rB = rA + 8;

    // phase 1: W=wnx, A=x
    copy_w_async<256>(g_wnx + (size_t)l * 32768, sb, NW_HI);
    load_split_64(g_x, base, NN, sm, 0, tid);
    CP_WAIT();
    __syncthreads();

    float acc[8][4];
    ZACC1(acc);
    warp_gemm3_64(sm, 0, NW_HI, wr, wc, lid, acc);       // x @ wnx
    __syncthreads();                                      // W + A free

    // phase 2: W=wna, A=agg
    copy_w_async<256>(g_wna + (size_t)l * 32768, sb, NW_HI);
    load_split_64(g_agg, base, NN, sm, 0, tid);
    CP_WAIT();
    __syncthreads();
    warp_gemm3_64(sm, 0, NW_HI, wr, wc, lid, acc);       // += agg @ wna
    __syncthreads();                                      // W + A free

    // phase 3: W=wn2, A=h
    copy_w_async<256>(g_wn2 + (size_t)l * 32768, sb, NW_HI);
#pragma unroll
    for (int n = 0; n < 8; n++) {
        int col = wc * 64 + n * 8 + lr;
        float2 bv = *(const float2*)(b1 + col);
        float* c = acc[n];
        uint32_t hi, lo;
        split2(fmaxf(c[0] + bv.x, 0.f), fmaxf(c[1] + bv.y, 0.f), hi, lo);
        *(uint32_t*)(sm + (size_t)rA * PITCH + col * 2) = hi;
        *(uint32_t*)(sm + 17408 + (size_t)rA * PITCH + col * 2) = lo;
        split2(fmaxf(c[2] + bv.x, 0.f), fmaxf(c[3] + bv.y, 0.f), hi, lo);
        *(uint32_t*)(sm + (size_t)rB * PITCH + col * 2) = hi;
        *(uint32_t*)(sm + 17408 + (size_t)rB * PITCH + col * 2) = lo;
    }
    CP_WAIT();
    __syncthreads();

    ZACC1(acc);
    warp_gemm3_64(sm, 0, NW_HI, wr, wc, lid, acc);       // h @ wn2
    __syncthreads();                                      // W + A(h) free

    // phase 4: W = wsrc (or nd_w1), A = x_new; write x_new to g_x; zero agg
    if (do_next)
        copy_w_async<256>(g_wsrc + (size_t)(l + 1) * 32768, sb, NW_HI);
    else
        copy_w_async<256>(g_wnd1, sb, NW_HI);
#pragma unroll
    for (int n = 0; n < 8; n++) {
        int col = wc * 64 + n * 8 + lr;
        float2 bv = *(const float2*)(b2 + col);
        float* c = acc[n];
        uint32_t hi, lo;
        if (base + rA < NN) {
            float* xp = g_x + (size_t)(base + rA) * HH + col;
            float2 xv = *(float2*)xp;
            float vx = c[0] + bv.x + xv.x, vy = c[1] + bv.y + xv.y;
            *(float2*)xp = make_float2(vx, vy);
            split2(vx, vy, hi, lo);
        } else split2(0.f, 0.f, hi, lo);
        *(uint32_t*)(sm + (size_t)rA * PITCH + col * 2) = hi;
        *(uint32_t*)(sm + 17408 + (size_t)rA * PITCH + col * 2) = lo;
        if (base + rB < NN) {
            float* xp = g_x + (size_t)(base + rB) * HH + col;
            float2 xv = *(float2*)xp;
            float vx = c[2] + bv.x + xv.x, vy = c[3] + bv.y + xv.y;
            *(float2*)xp = make_float2(vx, vy);
            split2(vx, vy, hi, lo);
        } else split2(0.f, 0.f, hi, lo);
        *(uint32_t*)(sm + (size_t)rB * PITCH + col * 2) = hi;
        *(uint32_t*)(sm + 17408 + (size_t)rB * PITCH + col * 2) = lo;
    }
    if (do_next) {
        for (int i = tid; i < 2048; i += 256) {
            int r = i >> 5, c4 = i & 31;
            if (base + r < NN)
                ((float4*)g_agg)[(size_t)(base + r) * 32 + c4] =
                    make_float4(0.f, 0.f, 0.f, 0.f);
        }
    }
    CP_WAIT();
    __syncthreads();   // A(x_new) + W ready

    ZACC1(acc);
    warp_gemm3_64(sm, 0, NW_HI, wr, wc, lid, acc);       // x_new @ W

    if (do_next) {
#pragma unroll
        for (int n = 0; n < 8; n++) {
            int col = wc * 64 + n * 8 + lr;
            float* c = acc[n];
            if (base + rA < NN)
                *(float2*)(g_xs + (size_t)(base + rA) * HH + col) =
                    make_float2(c[0], c[1]);
            if (base + rB < NN)
                *(float2*)(g_xs + (size_t)(base + rB) * HH + col) =
                    make_float2(c[2], c[3]);
        }
        __syncthreads();   // all warps done reading W before overwrite

        copy_w_async<256>(g_wdst + (size_t)(l + 1) * 32768, sb, NW_HI);
        CP_WAIT();
        __syncthreads();

        ZACC1(acc);
        warp_gemm3_64(sm, 0, NW_HI, wr, wc, lid, acc);   // x_new @ wdst
#pragma unroll
        for (int n = 0; n < 8; n++) {
            int col = wc * 64 + n * 8 + lr;
            float* c = acc[n];
            if (base + rA < NN)
                *(float2*)(g_xd + (size_t)(base + rA) * HH + col) =
                    make_float2(c[0], c[1]);
            if (base + rB < NN)
                *(float2*)(g_xd + (size_t)(base + rB) * HH + col) =
                    make_float2(c[2], c[3]);
        }
        return;
    }

    // ---- fused decoder: out = relu(x_new@nd_w1+ndb1)@nd_w2 + ndb2 ----------
    __syncthreads();   // all warps done reading A(x_new) before f32 overwrite
#pragma unroll
    for (int n = 0; n < 8; n++) {
        int col = wc * 64 + n * 8 + lr;
        float2 bv = *(const float2*)(ndb1 + col);
        float* c = acc[n];
        *(float2*)(sm + (size_t)rA * 544 + col * 4) =
            make_float2(fmaxf(c[0] + bv.x, 0.f), fmaxf(c[1] + bv.y, 0.f));
        *(float2*)(sm + (size_t)rB * 544 + col * 4) =
            make_float2(fmaxf(c[2] + bv.x, 0.f), fmaxf(c[3] + bv.y, 0.f));
    }
    __syncthreads();

    if (tid < 192) {
        int r = tid / 3, c = tid - r * 3;
        float s = ndb2[c];
#pragma unroll 4
        for (int k = 0; k < HH; k++)
            s += *(const float*)(sm + (size_t)r * 544 + k * 4) * ndw2[k * 3 + c];
        int nr = base + r;
        if (nr < NN) out[nr * 3 + c] = s;
    }
}

// ====== node encoder fused with xs/xd projection of layer 0 + agg zero =====
__global__ __launch_bounds__(256, 1) void encoder_node_fused(
    const float* __restrict__ in, const float* __restrict__ w1,
    const float* __restrict__ b1, const float* __restrict__ b2) {
    extern __shared__ __align__(16) char sm[];
    int tid = threadIdx.x, lid = tid & 31, wid = tid >> 5;
    int wr = wid >> 1, wc = wid & 1;
    int base = blockIdx.x * 128;
    int lq = lid >> 2, lr = (lid & 3) * 2;

    for (int g = tid; g < 2048; g += 256) {
        int r = g >> 4, c8 = (g & 15) << 3;
        int rr = min(base + r, NN - 1);
        float vin[6];
#pragma unroll
        for (int k = 0; k < 6; k++) vin[k] = in[(size_t)rr * 6 + k];
        float h[8];
#pragma unroll
        for (int c = 0; c < 8; c++) {
            int cc = c8 + c;
            float s = b1[cc];
#pragma unroll
            for (int k = 0; k < 6; k++) s += vin[k] * w1[k * HH + cc];
            h[c] = fmaxf(s, 0.f);
        }
        uint32_t hv[4], lv[4];
        split2(h[0], h[1], hv[0], lv[0]);
        split2(h[2], h[3], hv[1], lv[1]);
        split2(h[4], h[5], hv[2], lv[2]);
        split2(h[6], h[7], hv[3], lv[3]);
        char* dst = sm + (size_t)r * PITCH + c8 * 2;
        *(uint4*)(dst + A_HI) = make_uint4(hv[0], hv[1], hv[2], hv[3]);
        *(uint4*)(dst + A_LO) = make_uint4(lv[0], lv[1], lv[2], lv[3]);
    }
    copy_w(g_wne2, sm, B_HI);
    __syncthreads();

    float acc[2][8][4];
    ZACC(acc);
    warp_gemm3(sm, B_HI, wr, wc, lid, acc);
    __syncthreads();

#pragma unroll
    for (int m = 0; m < 2; m++) {
        int rA = wr * 32 + m * 16 + lq, rB = rA + 8;
#pragma unroll
        for (int n = 0; n < 8; n++) {
            int col = wc * 64 + n * 8 + lr;
            float2 bv = *(const float2*)(b2 + col);
            float* c = acc[m][n];
            float vx0 = c[0] + bv.x, vy0 = c[1] + bv.y;
            float vx1 = c[2] + bv.x, vy1 = c[3] + bv.y;
            uint32_t hi, lo;
            if (base + rA < NN)
                *(float2*)(g_x + (size_t)(base + rA) * HH + col) =
                    make_float2(vx0, vy0);
            split2(vx0, vy0, hi, lo);
            *(uint32_t*)(sm + A_HI + (size_t)rA * PITCH + col * 2) = hi;
            *(uint32_t*)(sm + A_LO + (size_t)rA * PITCH + col * 2) = lo;
            if (base + rB < NN)
                *(float2*)(g_x + (size_t)(base + rB) * HH + col) =
                    make_float2(vx1, vy1);
            split2(vx1, vy1, hi, lo);
            *(uint32_t*)(sm + A_HI + (size_t)rB * PITCH + col * 2) = hi;
            *(uint32_t*)(sm + A_LO + (size_t)rB * PITCH + col * 2) = lo;
        }
    }
    for (int i = tid; i < 4096; i += 256) {
        int r = i >> 5, c4 = i & 31;
        if (base + r < NN)
            ((float4*)g_agg)[(size_t)(base + r) * 32 + c4] =
                make_float4(0.f, 0.f, 0.f, 0.f);
    }
    copy_w(g_wsrc, sm, B_HI);
    __syncthreads();
    ZACC(acc);
    warp_gemm3(sm, B_HI, wr, wc, lid, acc);
#pragma unroll
    for (int m = 0; m < 2; m++) {
        int rA = wr * 32 + m * 16 + lq, rB = rA + 8;
#pragma unroll
        for (int n = 0; n < 8; n++) {
            int col = wc * 64 + n * 8 + lr;
            float* c = acc[m][n];
            if (base + rA < NN)
                *(float2*)(g_xs + (size_t)(base + rA) * HH + col) =
                    make_float2(c[0], c[1]);
            if (base + rB < NN)
                *(float2*)(g_xs + (size_t)(base + rB) * HH + col) =
                    make_float2(c[2], c[3]);
        }
    }
    __syncthreads();
    copy_w(g_wdst, sm, B_HI);
    __syncthreads();
    ZACC(acc);
    warp_gemm3(sm, B_HI, wr, wc, lid, acc);
#pragma unroll
    for (int m = 0; m < 2; m++) {
        int rA = wr * 32 + m * 16 + lq, rB = rA + 8;
#pragma unroll
        for (int n = 0; n < 8; n++) {
            int col = wc * 64 + n * 8 + lr;
            float* c = acc[m][n];
            if (base + rA < NN)
                *(float2*)(g_xd + (size_t)(base + rA) * HH + col) =
                    make_float2(c[0], c[1]);
            if (base + rB < NN)
                *(float2*)(g_xd + (size_t)(base + rB) * HH + col) =
                    make_float2(c[2], c[3]);
        }
    }
}

// ==== edge encoder: 2 independent 256-thread groups, W shared, PERMUTED ====
__global__ __launch_bounds__(512, 1) void encoder_edge(
    const float* __restrict__ in, const float* __restrict__ w1,
    const float* __restrict__ b1, const float* __restrict__ b2, int nt64) {
    extern __shared__ __align__(16) char sm[];
    uint32_t sb = smem_u32(sm);
    int tid = threadIdx.x;
    int grp = tid >> 8, gtid = tid & 255;
    int lid = tid & 31, wid_g = gtid >> 5;
    int wr = wid_g >> 1, wc = wid_g & 1;
    int barG = 1 + grp;
    uint32_t ga = (uint32_t)grp * 34816;

    copy_w_async<512>(g_wee2, sb, B_HI);
    CP_WAIT();
    __syncthreads();
    int lq = lid >> 2, lr = (lid & 3) * 2;
    int rA = wr * 16 + lq, rB = rA + 8;

    for (int st = blockIdx.x * 2 + grp; st < nt64; st += gridDim.x * 2) {
        int base = st * 64;
        BAR_GRP(barG);
        for (int g = gtid; g < 1024; g += 256) {
            int r = g >> 4, c8 = (g & 15) << 3;
            int rr = min(base + r, EE - 1);
            int src = g_perm[rr];
            float vin[3];
#pragma unroll
            for (int k = 0; k < 3; k++) vin[k] = in[(size_t)src * 3 + k];
            float h[8];
#pragma unroll
            for (int c = 0; c < 8; c++) {
                int cc = c8 + c;
                float s = b1[cc];
#pragma unroll
                for (int k = 0; k < 3; k++) s += vin[k] * w1[k * HH + cc];
                h[c] = fmaxf(s, 0.f);
            }
            uint32_t hv[4], lv[4];
            split2(h[0], h[1], hv[0], lv[0]);
            split2(h[2], h[3], hv[1], lv[1]);
            split2(h[4], h[5], hv[2], lv[2]);
            split2(h[6], h[7], hv[3], lv[3]);
            char* dst = sm + ga + (size_t)r * PITCH + c8 * 2;
            *(uint4*)(dst) = make_uint4(hv[0], hv[1], hv[2], hv[3]);
            *(uint4*)(dst + 17408) = make_uint4(lv[0], lv[1], lv[2], lv[3]);
        }
        BAR_GRP(barG);

        float acc[8][4];
        ZACC1(acc);
        warp_gemm3_64(sm, ga, B_HI, wr, wc, lid, acc);

#pragma unroll
        for (int n = 0; n < 8; n++) {
            int col = wc * 64 + n * 8 + lr;
            float2 bv = *(const float2*)(b2 + col);
            float* c = acc[n];
            uint32_t hi, lo;
            if (base + rA < EE) {
                split2(c[0] + bv.x, c[1] + bv.y, hi, lo);
                g_ehi[(size_t)(base + rA) * 64 + (col >> 1)] = hi;
                g_elo[(size_t)(base + rA) * 64 + (col >> 1)] = lo;
            }
            if (base + rB < EE) {
                split2(c[2] + bv.x, c[3] + bv.y, hi, lo);
                g_ehi[(size_t)(base + rB) * 64 + (col >> 1)] = hi;
                g_elo[(size_t)(base + rB) * 64 + (col >> 1)] = lo;
            }
        }
    }
}

// ============================================================================
extern "C" void kernel_launch(void* const* d_in, const int* in_sizes, int n_in,
                              void* d_out, int out_size) {
    const float* x_in    = (const float*)d_in[0];
    const float* eattr   = (const float*)d_in[1];
    const float* ne_w1   = (const float*)d_in[2];
    const float* ne_b1   = (const float*)d_in[3];
    const float* ne_w2   = (const float*)d_in[4];
    const float* ne_b2   = (const float*)d_in[5];
    const float* ee_w1   = (const float*)d_in[6];
    const float* ee_b1   = (const float*)d_in[7];
    const float* ee_w2   = (const float*)d_in[8];
    const float* ee_b2   = (const float*)d_in[9];
    const float* edge_w1 = (const float*)d_in[10];
    const float* edge_b1 = (const float*)d_in[11];
    const float* edge_w2 = (const float*)d_in[12];
    const float* edge_b2 = (const float*)d_in[13];
    const float* node_w1 = (const float*)d_in[14];
    const float* node_b1 = (const float*)d_in[15];
    const float* node_w2 = (const float*)d_in[16];
    const float* node_b2 = (const float*)d_in[17];
    const float* nd_w1   = (const float*)d_in[18];
    const float* nd_b1   = (const float*)d_in[19];
    const float* nd_w2   = (const float*)d_in[20];
    const float* nd_b2   = (const float*)d_in[21];
    const int*   eidx    = (const int*)d_in[22];
    const int*   rowi    = eidx;
    const int*   coli    = eidx + EE;

    cudaFuncSetAttribute(edge_layer_persist,
                         cudaFuncAttributeMaxDynamicSharedMemorySize, E_SMEM);
    cudaFuncSetAttribute(node_xsxd64,
                         cudaFuncAttributeMaxDynamicSharedMemorySize, N64_SMEM);
    cudaFuncSetAttribute(encoder_node_fused,
                         cudaFuncAttributeMaxDynamicSharedMemorySize, G_SMEM);
    cudaFuncSetAttribute(encoder_edge,
                         cudaFuncAttributeMaxDynamicSharedMemorySize, G_SMEM);
    cudaFuncSetAttribute(sort_build,
                         cudaFuncAttributeMaxDynamicSharedMemorySize,
                         (NN + 1024) * 4);

    const int TB_N = (NN + 127) / 128;   // 157
    const int NT64E = (EE + 63) / 64;    // 4688
    const int NT64N = (NN + 63) / 64;    // 313

    pack_all<<<59 * 64, 256>>>(edge_w1, node_w1, edge_w2, node_w2,
                               ne_w2, ee_w2, nd_w1);
    sort_build<<<1, 1024, (NN + 1024) * 4>>>(rowi);
    sort_permute<<<(EE + 255) / 256, 256>>>(rowi, coli);

    encoder_edge<<<NSM, 512, G_SMEM>>>(eattr, ee_w1, ee_b1, ee_b2, NT64E);
    encoder_node_fused<<<TB_N, 256, G_SMEM>>>(x_in, ne_w1, ne_b1, ne_b2);

    for (int l = 0; l < LL; l++) {
        edge_layer_persist<<<NSM, 512, E_SMEM>>>(l, edge_b1 + l * HH,
                                                 edge_b2 + l * HH,
                                                 NT64E, l < LL - 1 ? 1 : 0);
        node_xsxd64<<<NT64N, 256, N64_SMEM>>>(l, node_b1 + l * HH,
                                              node_b2 + l * HH,
                                              l < LL - 1 ? 1 : 0,
                                              nd_b1, nd_w2, nd_b2,
                                              (float*)d_out);
    }
}